// round 4
// baseline (speedup 1.0000x reference)
#include <cuda_runtime.h>

#define NG      512
#define NODES   200
#define EDGES   6400
#define HID     128
#define TPB     256

typedef unsigned long long ull;

// Scratch (no cudaMalloc allowed)
__device__ float g_hg[NG * HID];
__device__ float g_x1[NG * 512];
__device__ float g_x2[NG * 1024];
__device__ float g_x3[NG * 1024];
__device__ float g_x4[NG * 512];
__device__ float g_x4p[2 * NG * 512];     // split-K partials for layer d

// Piecewise-linear tables for t(a) = alpha(a)*a + beta(a)
__device__ float g_csorted[128];
__device__ float g_alpha[129 * 128];
__device__ float g_beta[129 * 128];

// ---- f32x2 packed-FMA helpers (sm_100+) -----------------------------------
__device__ __forceinline__ ull pack2(float lo, float hi) {
    ull d;
    asm("mov.b64 %0, {%1, %2};" : "=l"(d) : "f"(lo), "f"(hi));
    return d;
}
__device__ __forceinline__ void unpack2(ull v, float& lo, float& hi) {
    asm("mov.b64 {%0, %1}, %2;" : "=f"(lo), "=f"(hi) : "l"(v));
}
__device__ __forceinline__ void fma2(ull& acc, ull a, ull b) {
    asm("fma.rn.f32x2 %0, %1, %2, %0;" : "+l"(acc) : "l"(a), "l"(b));
}

// ---------------------------------------------------------------------------
// Precompute PWL tables: h1(a)=relu(a*w1+b1); t(a)=h1(a)@W2 is piecewise
// linear in scalar a with breakpoints c_k=-b1[k]/w1[k].
// ---------------------------------------------------------------------------
__global__ void __launch_bounds__(512) precompute_pwl(
    const float* __restrict__ W1, const float* __restrict__ b1,
    const float* __restrict__ W2)
{
    __shared__ float sc[128];
    __shared__ float sw[128], sb[128];
    __shared__ int   sidx[128];
    __shared__ float ssc[128];
    const int tid = threadIdx.x;

    if (tid < 128) {
        float w = W1[tid], b = b1[tid];
        sw[tid] = w; sb[tid] = b;
        sc[tid] = (w != 0.0f) ? (-b / w) : __int_as_float(0x7f800000);
    }
    __syncthreads();
    if (tid < 128) {
        float c = sc[tid];
        int r = 0;
        for (int j = 0; j < 128; j++) {
            float cj = sc[j];
            if (cj < c || (cj == c && j < tid)) r++;
        }
        sidx[r] = tid;
        ssc[r]  = c;
    }
    __syncthreads();
    if (tid < 128) g_csorted[tid] = ssc[tid];

    const int chunk = tid >> 7;
    const int j     = tid & 127;
    const int s0    = chunk * 32;

    float alpha = 0.0f, beta = 0.0f;
    for (int r = 0; r < 128; r++) {
        int k = sidx[r];
        float w = sw[k], b = sb[k];
        float W2kj = W2[k * 128 + j];
        if (w == 0.0f) { if (b > 0.0f) beta += b * W2kj; continue; }
        bool active = (w > 0.0f) ? (r < s0) : (r >= s0);
        if (active) { alpha = fmaf(w, W2kj, alpha); beta = fmaf(b, W2kj, beta); }
    }
    for (int s = s0; s < s0 + 32; s++) {
        g_alpha[s * 128 + j] = alpha;
        g_beta[s * 128 + j]  = beta;
        int k = sidx[s];
        float w = sw[k], b = sb[k];
        float W2kj = W2[k * 128 + j];
        float f = (w > 0.0f) ? 1.0f : ((w < 0.0f) ? -1.0f : 0.0f);
        alpha = fmaf(f * w, W2kj, alpha);
        beta  = fmaf(f * b, W2kj, beta);
    }
    if (chunk == 3) {
        g_alpha[128 * 128 + j] = alpha;
        g_beta[128 * 128 + j]  = beta;
    }
}

// ---------------------------------------------------------------------------
// Per-graph GNN kernel (256 threads, 2 CTAs/SM). SMEM total 113,840 B.
// ---------------------------------------------------------------------------
__global__ void __launch_bounds__(TPB, 2) gnn_kernel(
    const int*   __restrict__ src, const int*   __restrict__ dst,
    const float* __restrict__ b2,  float* __restrict__ hg)
{
    extern __shared__ float sf[];
    float* t    = sf;                              // 25600 floats
    float* s_s  = sf + 25600;
    float* s_a  = s_s + NODES;
    float* s_ii = s_a + NODES;
    float* s_io = s_ii + NODES;
    int*   cnt  = (int*)(s_io + NODES);            // 204
    int*   cur  = cnt + 204;                       // 204
    unsigned char* seg8 = (unsigned char*)(cur + 204); // 208
    unsigned char* csr  = seg8 + 208;              // 6400

    const int tid   = threadIdx.x;
    const int g     = blockIdx.x;
    const int nbase = g * NODES;
    const int4* src4 = (const int4*)(src + g * EDGES);
    const int4* dst4 = (const int4*)(dst + g * EDGES);

    // --- degrees (cnt = in-deg, cur = out-deg), 4 edges/thread/iter ---
    for (int i = tid; i < 204; i += TPB) { cnt[i] = 0; cur[i] = 0; }
    __syncthreads();
    for (int e4 = tid; e4 < EDGES / 4; e4 += TPB) {
        int4 s4 = src4[e4], d4 = dst4[e4];
        atomicAdd(&cnt[d4.x - nbase], 1); atomicAdd(&cur[s4.x - nbase], 1);
        atomicAdd(&cnt[d4.y - nbase], 1); atomicAdd(&cur[s4.y - nbase], 1);
        atomicAdd(&cnt[d4.z - nbase], 1); atomicAdd(&cur[s4.z - nbase], 1);
        atomicAdd(&cnt[d4.w - nbase], 1); atomicAdd(&cur[s4.w - nbase], 1);
    }
    __syncthreads();
    for (int i = tid; i < NODES; i += TPB) {
        float idg = (float)cnt[i];
        float odg = (float)cur[i];
        float ii = rsqrtf(fmaxf(idg, 1.0f));
        float io = rsqrtf(fmaxf(odg, 1.0f));
        s_ii[i] = ii;
        s_io[i] = io;
        s_s[i]  = idg * io;
    }
    __syncthreads();
    // --- warp 0: exclusive scan of cnt -> offsets in cnt & cur ---
    if (tid < 32) {
        const int PER = 7;
        int base = tid * PER;
        int vals[PER];
        int s = 0;
        #pragma unroll
        for (int j = 0; j < PER; j++) {
            int i = base + j;
            int c = (i < NODES) ? cnt[i] : 0;
            vals[j] = c; s += c;
        }
        int pre = s;
        #pragma unroll
        for (int o = 1; o < 32; o <<= 1) {
            int tt = __shfl_up_sync(0xffffffffu, pre, o);
            if (tid >= o) pre += tt;
        }
        int run = pre - s;
        #pragma unroll
        for (int j = 0; j < PER; j++) {
            int i = base + j;
            if (i < NODES) { cnt[i] = run; cur[i] = run; run += vals[j]; }
        }
        if (tid == 31) cnt[NODES] = run;
    }
    __syncthreads();
    // --- CSR fill ---
    for (int e4 = tid; e4 < EDGES / 4; e4 += TPB) {
        int4 s4 = src4[e4], d4 = dst4[e4];
        int p;
        p = atomicAdd(&cur[d4.x - nbase], 1); csr[p] = (unsigned char)(s4.x - nbase);
        p = atomicAdd(&cur[d4.y - nbase], 1); csr[p] = (unsigned char)(s4.y - nbase);
        p = atomicAdd(&cur[d4.z - nbase], 1); csr[p] = (unsigned char)(s4.z - nbase);
        p = atomicAdd(&cur[d4.w - nbase], 1); csr[p] = (unsigned char)(s4.w - nbase);
    }
    __syncthreads();
    // --- layer-1 scalar aggregation + segment search ---
    for (int d = tid; d < NODES; d += TPB) {
        float sum = 0.0f;
        int p0 = cnt[d], p1 = cnt[d + 1];
        for (int p = p0; p < p1; p++) sum += s_s[csr[p]];
        float a = sum * s_ii[d];
        s_a[d] = a;
        int lo = 0, hi = 128;
        while (lo < hi) {
            int m = (lo + hi) >> 1;
            if (g_csorted[m] < a) lo = m + 1; else hi = m;
        }
        seg8[d] = (unsigned char)lo;
    }
    __syncthreads();
    // --- t_i = (alpha_s * a_i + beta_s) * inv_out_i ---
    for (int idx = tid; idx < NODES * 32; idx += TPB) {
        int i = idx >> 5, q = idx & 31;
        float a  = s_a[i];
        float io = s_io[i];
        int   s  = seg8[i];
        float4 al = ((const float4*)(g_alpha + s * 128))[q];
        float4 be = ((const float4*)(g_beta  + s * 128))[q];
        float4 o;
        o.x = fmaf(al.x, a, be.x) * io;
        o.y = fmaf(al.y, a, be.y) * io;
        o.z = fmaf(al.z, a, be.z) * io;
        o.w = fmaf(al.w, a, be.w) * io;
        ((float4*)t)[idx] = o;
    }
    __syncthreads();
    // --- layer-2 gather + relu + fused mean pool ---
    const int tx = tid & 31;
    const int w  = tid >> 5;
    {
        float4 bb2 = ((const float4*)b2)[tx];
        float4 pacc = {0, 0, 0, 0};
        for (int d = w; d < NODES; d += 8) {
            int p0 = cnt[d], p1 = cnt[d + 1];
            float4 acc = {0, 0, 0, 0};
            for (int p = p0; p < p1; ++p) {
                int sv = csr[p];
                float4 v = ((const float4*)t)[sv * 32 + tx];
                acc.x += v.x; acc.y += v.y; acc.z += v.z; acc.w += v.w;
            }
            float ii = s_ii[d];
            pacc.x += fmaxf(fmaf(acc.x, ii, bb2.x), 0.0f);
            pacc.y += fmaxf(fmaf(acc.y, ii, bb2.y), 0.0f);
            pacc.z += fmaxf(fmaf(acc.z, ii, bb2.z), 0.0f);
            pacc.w += fmaxf(fmaf(acc.w, ii, bb2.w), 0.0f);
        }
        __syncthreads();
        ((float4*)t)[w * 32 + tx] = pacc;
    }
    __syncthreads();
    if (tid < HID) {
        float s = 0.0f;
        #pragma unroll
        for (int c = 0; c < 8; c++) s += t[c * HID + tid];
        hg[g * HID + tid] = s * (1.0f / 200.0f);
    }
}

// ---------------------------------------------------------------------------
// Double-buffered fp32 GEMM with packed f32x2 FMA: C = [relu](A @ W + bias).
// 64x64 tile, 256 threads, 4 rows x 4 cols per thread (as 4x2 f32x2 pairs).
// A-tile stored duplicated (a,a) as b64 so the inner loop has no MOV packs.
// Split-K via blockIdx.z. bias==nullptr -> raw partial output.
// ---------------------------------------------------------------------------
__global__ void __launch_bounds__(256) gemm_db(
    const float* __restrict__ A, int lda,
    const float* __restrict__ W,
    const float* __restrict__ bias,
    float* __restrict__ C,
    int K, int Nc, int do_relu, int zCstride)
{
    __shared__ ull   As2[2][64 * 16];   // (a,a) duplicated pairs, 16 KB
    __shared__ float Ws[2][16 * 64];    // 8 KB
    const int tid = threadIdx.x;
    const int tx = tid & 15, ty = tid >> 4;
    const int row0 = blockIdx.y * 64, col0 = blockIdx.x * 64;

    A += (size_t)blockIdx.z * K;
    W += (size_t)blockIdx.z * K * Nc;
    C += (size_t)blockIdx.z * zCstride;

    const int ar = tid >> 2, akq = (tid & 3) * 4;
    const int wk = tid >> 4, wc = (tid & 15) * 4;

    float4 ga = *(const float4*)(A + (size_t)(row0 + ar) * lda + akq);
    float4 gw = *(const float4*)(W + (size_t)wk * Nc + col0 + wc);
    {
        ull* dstA = &As2[0][ar * 16 + akq];
        dstA[0] = pack2(ga.x, ga.x); dstA[1] = pack2(ga.y, ga.y);
        dstA[2] = pack2(ga.z, ga.z); dstA[3] = pack2(ga.w, ga.w);
        ((float4*)Ws[0])[tid] = gw;
    }
    __syncthreads();

    ull acc[4][2] = {{0,0},{0,0},{0,0},{0,0}};
    const int ntiles = K >> 4;
    int buf = 0;
    for (int kt = 0; kt < ntiles; kt++) {
        if (kt + 1 < ntiles) {
            ga = *(const float4*)(A + (size_t)(row0 + ar) * lda + (kt + 1) * 16 + akq);
            gw = *(const float4*)(W + (size_t)((kt + 1) * 16 + wk) * Nc + col0 + wc);
        }
        #pragma unroll
        for (int kk = 0; kk < 16; kk++) {
            const ull* w8 = (const ull*)(Ws[buf] + kk * 64);
            ull w0 = w8[tx * 2 + 0];
            ull w1 = w8[tx * 2 + 1];
            #pragma unroll
            for (int i = 0; i < 4; i++) {
                ull aa = As2[buf][(ty * 4 + i) * 16 + kk];
                fma2(acc[i][0], aa, w0);
                fma2(acc[i][1], aa, w1);
            }
        }
        if (kt + 1 < ntiles) {
            ull* dstA = &As2[buf ^ 1][ar * 16 + akq];
            dstA[0] = pack2(ga.x, ga.x); dstA[1] = pack2(ga.y, ga.y);
            dstA[2] = pack2(ga.z, ga.z); dstA[3] = pack2(ga.w, ga.w);
            ((float4*)Ws[buf ^ 1])[tid] = gw;
        }
        __syncthreads();
        buf ^= 1;
    }
    float4 bv = {0, 0, 0, 0};
    if (bias) bv = *(const float4*)(bias + col0 + tx * 4);
    #pragma unroll
    for (int i = 0; i < 4; i++) {
        float4 o;
        unpack2(acc[i][0], o.x, o.y);
        unpack2(acc[i][1], o.z, o.w);
        o.x += bv.x; o.y += bv.y; o.z += bv.z; o.w += bv.w;
        if (do_relu) {
            o.x = fmaxf(o.x, 0.0f); o.y = fmaxf(o.y, 0.0f);
            o.z = fmaxf(o.z, 0.0f); o.w = fmaxf(o.w, 0.0f);
        }
        *(float4*)(C + (size_t)(row0 + ty * 4 + i) * Nc + col0 + tx * 4) = o;
    }
}

// Combine split-K partials: x = relu(p0 + p1 + bias)
__global__ void __launch_bounds__(256) combine_relu(
    const float* __restrict__ p, const float* __restrict__ bias,
    float* __restrict__ C, int Nc, int total4)
{
    int idx = blockIdx.x * 256 + threadIdx.x;
    if (idx >= total4) return;
    const int nq = Nc >> 2;
    float4 a = ((const float4*)p)[idx];
    float4 b = ((const float4*)p)[idx + total4];
    float4 bv = ((const float4*)bias)[idx % nq];
    float4 o;
    o.x = fmaxf(a.x + b.x + bv.x, 0.0f);
    o.y = fmaxf(a.y + b.y + bv.y, 0.0f);
    o.z = fmaxf(a.z + b.z + bv.z, 0.0f);
    o.w = fmaxf(a.w + b.w + bv.w, 0.0f);
    ((float4*)C)[idx] = o;
}

// ---------------------------------------------------------------------------
// Final layer: out = softmax(A(512x512) @ We(512x10) + be). Warp per row.
// ---------------------------------------------------------------------------
__global__ void __launch_bounds__(256) head_softmax(
    const float* __restrict__ A, const float* __restrict__ We,
    const float* __restrict__ be, float* __restrict__ out)
{
    __shared__ float Ws[512 * 10];
    const int tid = threadIdx.x;
    for (int i = tid; i < 512 * 10; i += 256) Ws[i] = We[i];
    __syncthreads();
    const int lane = tid & 31, w = tid >> 5;
    const int row = blockIdx.x * 8 + w;

    float acc[10];
    #pragma unroll
    for (int c = 0; c < 10; c++) acc[c] = 0.0f;
    for (int k = lane; k < 512; k += 32) {
        float a = A[row * 512 + k];
        #pragma unroll
        for (int c = 0; c < 10; c++) acc[c] = fmaf(a, Ws[k * 10 + c], acc[c]);
    }
    #pragma unroll
    for (int c = 0; c < 10; c++) {
        #pragma unroll
        for (int o = 16; o > 0; o >>= 1)
            acc[c] += __shfl_xor_sync(0xffffffffu, acc[c], o);
    }
    if (lane == 0) {
        float v[10], mx = -1e30f;
        #pragma unroll
        for (int c = 0; c < 10; c++) { v[c] = acc[c] + be[c]; mx = fmaxf(mx, v[c]); }
        float s = 0.0f;
        #pragma unroll
        for (int c = 0; c < 10; c++) { v[c] = __expf(v[c] - mx); s += v[c]; }
        float inv = 1.0f / s;
        #pragma unroll
        for (int c = 0; c < 10; c++) out[row * 10 + c] = v[c] * inv;
    }
}

// ---------------------------------------------------------------------------
extern "C" void kernel_launch(void* const* d_in, const int* in_sizes, int n_in,
                              void* d_out, int out_size)
{
    const int*   src = (const int*)  d_in[0];
    const int*   dst = (const int*)  d_in[1];
    const float* W1  = (const float*)d_in[2];
    const float* b1  = (const float*)d_in[3];
    const float* W2  = (const float*)d_in[4];
    const float* b2  = (const float*)d_in[5];
    const float* Wa  = (const float*)d_in[6];
    const float* ba  = (const float*)d_in[7];
    const float* Wb  = (const float*)d_in[8];
    const float* bb  = (const float*)d_in[9];
    const float* Wc  = (const float*)d_in[10];
    const float* bc  = (const float*)d_in[11];
    const float* Wd  = (const float*)d_in[12];
    const float* bd  = (const float*)d_in[13];
    const float* We  = (const float*)d_in[14];
    const float* be  = (const float*)d_in[15];
    float* out = (float*)d_out;

    float *hg, *x1, *x2, *x3, *x4, *x4p;
    cudaGetSymbolAddress((void**)&hg,  g_hg);
    cudaGetSymbolAddress((void**)&x1,  g_x1);
    cudaGetSymbolAddress((void**)&x2,  g_x2);
    cudaGetSymbolAddress((void**)&x3,  g_x3);
    cudaGetSymbolAddress((void**)&x4,  g_x4);
    cudaGetSymbolAddress((void**)&x4p, g_x4p);

    const int SMEM = 113840;
    cudaFuncSetAttribute(gnn_kernel, cudaFuncAttributeMaxDynamicSharedMemorySize, SMEM);

    precompute_pwl<<<1, 512>>>(W1, b1, W2);
    gnn_kernel<<<NG, TPB, SMEM>>>(src, dst, b2, hg);

    gemm_db<<<dim3(8, 8, 1),  256>>>(hg, 128,  Wa, ba, x1, 128,  512,  1, 0);
    gemm_db<<<dim3(16, 8, 1), 256>>>(x1, 512,  Wb, bb, x2, 512,  1024, 1, 0);
    gemm_db<<<dim3(16, 8, 1), 256>>>(x2, 1024, Wc, bc, x3, 1024, 1024, 1, 0);
    gemm_db<<<dim3(8, 8, 2),  256>>>(x3, 1024, Wd, nullptr, x4p, 512, 512, 0, 512 * 512);
    combine_relu<<<(512 * 512 / 4 + 255) / 256, 256>>>(x4p, bd, x4, 512, 512 * 512 / 4);

    head_softmax<<<64, 256>>>(x4, We, be, out);
}

// round 5
// speedup vs baseline: 1.0575x; 1.0575x over previous
#include <cuda_runtime.h>
#include <cuda_bf16.h>

#define NG      512
#define NODES   200
#define EDGES   6400
#define HID     128
#define TPB     256

// Scratch (no cudaMalloc allowed)
__device__ float g_hg[NG * HID];
__device__ float g_x1[NG * 512];
__device__ float g_x2[NG * 1024];
__device__ float g_x3[NG * 1024];
__device__ float g_x4[NG * 512];
__device__ float g_x4p[2 * NG * 512];     // split-K partials for layer d

// Piecewise-linear tables for t(a) = alpha(a)*a + beta(a)
__device__ float g_csorted[128];
__device__ float g_alpha[129 * 128];
__device__ float g_beta[129 * 128];

// ---------------------------------------------------------------------------
// Precompute PWL tables (unchanged, correct since R3)
// ---------------------------------------------------------------------------
__global__ void __launch_bounds__(512) precompute_pwl(
    const float* __restrict__ W1, const float* __restrict__ b1,
    const float* __restrict__ W2)
{
    __shared__ float sc[128];
    __shared__ float sw[128], sb[128];
    __shared__ int   sidx[128];
    __shared__ float ssc[128];
    const int tid = threadIdx.x;

    if (tid < 128) {
        float w = W1[tid], b = b1[tid];
        sw[tid] = w; sb[tid] = b;
        sc[tid] = (w != 0.0f) ? (-b / w) : __int_as_float(0x7f800000);
    }
    __syncthreads();
    if (tid < 128) {
        float c = sc[tid];
        int r = 0;
        for (int j = 0; j < 128; j++) {
            float cj = sc[j];
            if (cj < c || (cj == c && j < tid)) r++;
        }
        sidx[r] = tid;
        ssc[r]  = c;
    }
    __syncthreads();
    if (tid < 128) g_csorted[tid] = ssc[tid];

    const int chunk = tid >> 7;
    const int j     = tid & 127;
    const int s0    = chunk * 32;

    float alpha = 0.0f, beta = 0.0f;
    for (int r = 0; r < 128; r++) {
        int k = sidx[r];
        float w = sw[k], b = sb[k];
        float W2kj = W2[k * 128 + j];
        if (w == 0.0f) { if (b > 0.0f) beta += b * W2kj; continue; }
        bool active = (w > 0.0f) ? (r < s0) : (r >= s0);
        if (active) { alpha = fmaf(w, W2kj, alpha); beta = fmaf(b, W2kj, beta); }
    }
    for (int s = s0; s < s0 + 32; s++) {
        g_alpha[s * 128 + j] = alpha;
        g_beta[s * 128 + j]  = beta;
        int k = sidx[s];
        float w = sw[k], b = sb[k];
        float W2kj = W2[k * 128 + j];
        float f = (w > 0.0f) ? 1.0f : ((w < 0.0f) ? -1.0f : 0.0f);
        alpha = fmaf(f * w, W2kj, alpha);
        beta  = fmaf(f * b, W2kj, beta);
    }
    if (chunk == 3) {
        g_alpha[128 * 128 + j] = alpha;
        g_beta[128 * 128 + j]  = beta;
    }
}

// ---------------------------------------------------------------------------
// Per-graph GNN kernel — exact R3 version (scalar edge loads).
// ---------------------------------------------------------------------------
__global__ void __launch_bounds__(TPB, 2) gnn_kernel(
    const int*   __restrict__ src, const int*   __restrict__ dst,
    const float* __restrict__ b2,  float* __restrict__ hg)
{
    extern __shared__ float sf[];
    float* t    = sf;
    float* s_s  = sf + 25600;
    float* s_a  = s_s + NODES;
    float* s_ii = s_a + NODES;
    float* s_io = s_ii + NODES;
    int*   cnt  = (int*)(s_io + NODES);
    int*   cur  = cnt + 204;
    unsigned char* seg8 = (unsigned char*)(cur + 204);
    unsigned char* csr  = seg8 + 208;

    const int tid   = threadIdx.x;
    const int g     = blockIdx.x;
    const int ebase = g * EDGES;
    const int nbase = g * NODES;

    for (int i = tid; i < 204; i += TPB) { cnt[i] = 0; cur[i] = 0; }
    __syncthreads();
    for (int e = tid; e < EDGES; e += TPB) {
        int sl = src[ebase + e] - nbase;
        int dl = dst[ebase + e] - nbase;
        atomicAdd(&cnt[dl], 1);
        atomicAdd(&cur[sl], 1);
    }
    __syncthreads();
    for (int i = tid; i < NODES; i += TPB) {
        float idg = (float)cnt[i];
        float odg = (float)cur[i];
        float ii = rsqrtf(fmaxf(idg, 1.0f));
        float io = rsqrtf(fmaxf(odg, 1.0f));
        s_ii[i] = ii;
        s_io[i] = io;
        s_s[i]  = idg * io;
    }
    __syncthreads();
    if (tid < 32) {
        const int PER = 7;
        int base = tid * PER;
        int vals[PER];
        int s = 0;
        #pragma unroll
        for (int j = 0; j < PER; j++) {
            int i = base + j;
            int c = (i < NODES) ? cnt[i] : 0;
            vals[j] = c; s += c;
        }
        int pre = s;
        #pragma unroll
        for (int o = 1; o < 32; o <<= 1) {
            int tt = __shfl_up_sync(0xffffffffu, pre, o);
            if (tid >= o) pre += tt;
        }
        int run = pre - s;
        #pragma unroll
        for (int j = 0; j < PER; j++) {
            int i = base + j;
            if (i < NODES) { cnt[i] = run; cur[i] = run; run += vals[j]; }
        }
        if (tid == 31) cnt[NODES] = run;
    }
    __syncthreads();
    for (int e = tid; e < EDGES; e += TPB) {
        int sl = src[ebase + e] - nbase;
        int dl = dst[ebase + e] - nbase;
        int p  = atomicAdd(&cur[dl], 1);
        csr[p] = (unsigned char)sl;
    }
    __syncthreads();
    for (int d = tid; d < NODES; d += TPB) {
        float sum = 0.0f;
        int p0 = cnt[d], p1 = cnt[d + 1];
        for (int p = p0; p < p1; p++) sum += s_s[csr[p]];
        float a = sum * s_ii[d];
        s_a[d] = a;
        int lo = 0, hi = 128;
        while (lo < hi) {
            int m = (lo + hi) >> 1;
            if (g_csorted[m] < a) lo = m + 1; else hi = m;
        }
        seg8[d] = (unsigned char)lo;
    }
    __syncthreads();
    for (int idx = tid; idx < NODES * 32; idx += TPB) {
        int i = idx >> 5, q = idx & 31;
        float a  = s_a[i];
        float io = s_io[i];
        int   s  = seg8[i];
        float4 al = ((const float4*)(g_alpha + s * 128))[q];
        float4 be = ((const float4*)(g_beta  + s * 128))[q];
        float4 o;
        o.x = fmaf(al.x, a, be.x) * io;
        o.y = fmaf(al.y, a, be.y) * io;
        o.z = fmaf(al.z, a, be.z) * io;
        o.w = fmaf(al.w, a, be.w) * io;
        ((float4*)t)[idx] = o;
    }
    __syncthreads();
    const int tx = tid & 31;
    const int w  = tid >> 5;
    {
        float4 bb2 = ((const float4*)b2)[tx];
        float4 pacc = {0, 0, 0, 0};
        for (int d = w; d < NODES; d += 8) {
            int p0 = cnt[d], p1 = cnt[d + 1];
            float4 acc = {0, 0, 0, 0};
            for (int p = p0; p < p1; ++p) {
                int sv = csr[p];
                float4 v = ((const float4*)t)[sv * 32 + tx];
                acc.x += v.x; acc.y += v.y; acc.z += v.z; acc.w += v.w;
            }
            float ii = s_ii[d];
            pacc.x += fmaxf(fmaf(acc.x, ii, bb2.x), 0.0f);
            pacc.y += fmaxf(fmaf(acc.y, ii, bb2.y), 0.0f);
            pacc.z += fmaxf(fmaf(acc.z, ii, bb2.z), 0.0f);
            pacc.w += fmaxf(fmaf(acc.w, ii, bb2.w), 0.0f);
        }
        __syncthreads();
        ((float4*)t)[w * 32 + tx] = pacc;
    }
    __syncthreads();
    if (tid < HID) {
        float s = 0.0f;
        #pragma unroll
        for (int c = 0; c < 8; c++) s += t[c * HID + tid];
        hg[g * HID + tid] = s * (1.0f / 200.0f);
    }
}

// ---------------------------------------------------------------------------
// bf16 hi/lo compensated tensor-core GEMM:
//   C = [relu]( A @ W + bias ),  A: M x K fp32, W: K x N fp32, fp32-accurate
//   via Ahi@Whi + Ahi@Wlo + Alo@Whi (bf16 mma.m16n8k16, fp32 accum).
// CTA: 256 thr, 64x64 tile; warps 2x4, warp tile 32x16; double-buffered SMEM.
// Split-K via blockIdx.z (K = per-chunk, zCstride = C offset per z).
// ---------------------------------------------------------------------------
#define TS 24   // SMEM row stride (bf16 elems): conflict-free fragment loads

__device__ __forceinline__ void mma_bf16(float c[4], const unsigned a[4],
                                         const unsigned b0, const unsigned b1) {
    asm volatile(
        "mma.sync.aligned.m16n8k16.row.col.f32.bf16.bf16.f32 "
        "{%0,%1,%2,%3}, {%4,%5,%6,%7}, {%8,%9}, {%0,%1,%2,%3};\n"
        : "+f"(c[0]), "+f"(c[1]), "+f"(c[2]), "+f"(c[3])
        : "r"(a[0]), "r"(a[1]), "r"(a[2]), "r"(a[3]), "r"(b0), "r"(b1));
}

__device__ __forceinline__ __nv_bfloat162 hi2(float x, float y) {
    return __nv_bfloat162(__float2bfloat16(x), __float2bfloat16(y));
}
__device__ __forceinline__ __nv_bfloat162 lo2(float x, float y) {
    float hx = __bfloat162float(__float2bfloat16(x));
    float hy = __bfloat162float(__float2bfloat16(y));
    return __nv_bfloat162(__float2bfloat16(x - hx), __float2bfloat16(y - hy));
}

__global__ void __launch_bounds__(256) gemm_mma(
    const float* __restrict__ A, int lda,
    const float* __restrict__ W,
    const float* __restrict__ bias,
    float* __restrict__ C,
    int K, int Nc, int do_relu, int zCstride)
{
    __shared__ __nv_bfloat16 sAhi[2][64 * TS];
    __shared__ __nv_bfloat16 sAlo[2][64 * TS];
    __shared__ __nv_bfloat16 sBhi[2][64 * TS];   // n-major: [n][k]
    __shared__ __nv_bfloat16 sBlo[2][64 * TS];

    const int tid  = threadIdx.x;
    const int lane = tid & 31;
    const int wid  = tid >> 5;
    const int g    = lane >> 2;
    const int tg   = lane & 3;
    const int wm0  = (wid & 1) * 32;   // warp row offset (2)
    const int wn0  = (wid >> 1) * 16;  // warp col offset (4)
    const int row0 = blockIdx.y * 64, col0 = blockIdx.x * 64;

    A += (size_t)blockIdx.z * K;
    W += (size_t)blockIdx.z * K * Nc;
    C += (size_t)blockIdx.z * zCstride;

    // Loader coords
    const int arow = tid >> 2, akq = (tid & 3) * 4;   // A: 64 rows x 16 k
    const int wk   = tid >> 4, wn4 = (tid & 15) * 4;  // W: 16 k x 64 n

    // prefetch tile 0
    float4 ga = *(const float4*)(A + (size_t)(row0 + arow) * lda + akq);
    float4 gw = *(const float4*)(W + (size_t)wk * Nc + col0 + wn4);

    float c[2][2][4];
    #pragma unroll
    for (int mi = 0; mi < 2; mi++)
        #pragma unroll
        for (int ni = 0; ni < 2; ni++)
            #pragma unroll
            for (int q = 0; q < 4; q++) c[mi][ni][q] = 0.0f;

    const int ntiles = K >> 4;
    int buf = 0;
    // store tile 0
    {
        int o = arow * TS + akq;
        *(__nv_bfloat162*)(&sAhi[0][o])     = hi2(ga.x, ga.y);
        *(__nv_bfloat162*)(&sAhi[0][o + 2]) = hi2(ga.z, ga.w);
        *(__nv_bfloat162*)(&sAlo[0][o])     = lo2(ga.x, ga.y);
        *(__nv_bfloat162*)(&sAlo[0][o + 2]) = lo2(ga.z, ga.w);
        const float* wv = (const float*)&gw;
        #pragma unroll
        for (int i = 0; i < 4; i++) {
            float v = wv[i];
            __nv_bfloat16 h = __float2bfloat16(v);
            sBhi[0][(wn4 + i) * TS + wk] = h;
            sBlo[0][(wn4 + i) * TS + wk] = __float2bfloat16(v - __bfloat162float(h));
        }
    }
    __syncthreads();

    for (int kt = 0; kt < ntiles; kt++) {
        if (kt + 1 < ntiles) {
            ga = *(const float4*)(A + (size_t)(row0 + arow) * lda + (kt + 1) * 16 + akq);
            gw = *(const float4*)(W + (size_t)((kt + 1) * 16 + wk) * Nc + col0 + wn4);
        }
        // fragment loads
        unsigned ahi[2][4], alo[2][4], bhi[2][2], blo[2][2];
        #pragma unroll
        for (int mi = 0; mi < 2; mi++) {
            int r = wm0 + mi * 16 + g;
            const __nv_bfloat16* ph = &sAhi[buf][r * TS + tg * 2];
            const __nv_bfloat16* pl = &sAlo[buf][r * TS + tg * 2];
            ahi[mi][0] = *(const unsigned*)(ph);
            ahi[mi][1] = *(const unsigned*)(ph + 8 * TS);
            ahi[mi][2] = *(const unsigned*)(ph + 8);
            ahi[mi][3] = *(const unsigned*)(ph + 8 * TS + 8);
            alo[mi][0] = *(const unsigned*)(pl);
            alo[mi][1] = *(const unsigned*)(pl + 8 * TS);
            alo[mi][2] = *(const unsigned*)(pl + 8);
            alo[mi][3] = *(const unsigned*)(pl + 8 * TS + 8);
        }
        #pragma unroll
        for (int ni = 0; ni < 2; ni++) {
            int n = wn0 + ni * 8 + g;
            const __nv_bfloat16* ph = &sBhi[buf][n * TS + tg * 2];
            const __nv_bfloat16* pl = &sBlo[buf][n * TS + tg * 2];
            bhi[ni][0] = *(const unsigned*)(ph);
            bhi[ni][1] = *(const unsigned*)(ph + 8);
            blo[ni][0] = *(const unsigned*)(pl);
            blo[ni][1] = *(const unsigned*)(pl + 8);
        }
        // mma: hi*hi + hi*lo + lo*hi
        #pragma unroll
        for (int mi = 0; mi < 2; mi++)
            #pragma unroll
            for (int ni = 0; ni < 2; ni++) {
                mma_bf16(c[mi][ni], ahi[mi], bhi[ni][0], bhi[ni][1]);
                mma_bf16(c[mi][ni], ahi[mi], blo[ni][0], blo[ni][1]);
                mma_bf16(c[mi][ni], alo[mi], bhi[ni][0], bhi[ni][1]);
            }
        // store next tile
        if (kt + 1 < ntiles) {
            int nb = buf ^ 1;
            int o = arow * TS + akq;
            *(__nv_bfloat162*)(&sAhi[nb][o])     = hi2(ga.x, ga.y);
            *(__nv_bfloat162*)(&sAhi[nb][o + 2]) = hi2(ga.z, ga.w);
            *(__nv_bfloat162*)(&sAlo[nb][o])     = lo2(ga.x, ga.y);
            *(__nv_bfloat162*)(&sAlo[nb][o + 2]) = lo2(ga.z, ga.w);
            const float* wv = (const float*)&gw;
            #pragma unroll
            for (int i = 0; i < 4; i++) {
                float v = wv[i];
                __nv_bfloat16 h = __float2bfloat16(v);
                sBhi[nb][(wn4 + i) * TS + wk] = h;
                sBlo[nb][(wn4 + i) * TS + wk] = __float2bfloat16(v - __bfloat162float(h));
            }
        }
        __syncthreads();
        buf ^= 1;
    }

    // epilogue
    #pragma unroll
    for (int mi = 0; mi < 2; mi++) {
        #pragma unroll
        for (int ni = 0; ni < 2; ni++) {
            int r  = row0 + wm0 + mi * 16 + g;
            int cc = col0 + wn0 + ni * 8 + tg * 2;
            float bx = 0.0f, by = 0.0f;
            if (bias) { float2 bv = *(const float2*)(bias + cc); bx = bv.x; by = bv.y; }
            float2 o0, o1;
            o0.x = c[mi][ni][0] + bx; o0.y = c[mi][ni][1] + by;
            o1.x = c[mi][ni][2] + bx; o1.y = c[mi][ni][3] + by;
            if (do_relu) {
                o0.x = fmaxf(o0.x, 0.0f); o0.y = fmaxf(o0.y, 0.0f);
                o1.x = fmaxf(o1.x, 0.0f); o1.y = fmaxf(o1.y, 0.0f);
            }
            *(float2*)(C + (size_t)r * Nc + cc)       = o0;
            *(float2*)(C + (size_t)(r + 8) * Nc + cc) = o1;
        }
    }
}

// Combine split-K partials: x = relu(p0 + p1 + bias)
__global__ void __launch_bounds__(256) combine_relu(
    const float* __restrict__ p, const float* __restrict__ bias,
    float* __restrict__ C, int Nc, int total4)
{
    int idx = blockIdx.x * 256 + threadIdx.x;
    if (idx >= total4) return;
    const int nq = Nc >> 2;
    float4 a = ((const float4*)p)[idx];
    float4 b = ((const float4*)p)[idx + total4];
    float4 bv = ((const float4*)bias)[idx % nq];
    float4 o;
    o.x = fmaxf(a.x + b.x + bv.x, 0.0f);
    o.y = fmaxf(a.y + b.y + bv.y, 0.0f);
    o.z = fmaxf(a.z + b.z + bv.z, 0.0f);
    o.w = fmaxf(a.w + b.w + bv.w, 0.0f);
    ((float4*)C)[idx] = o;
}

// ---------------------------------------------------------------------------
// Final layer: out = softmax(A(512x512) @ We(512x10) + be). Warp per row.
// ---------------------------------------------------------------------------
__global__ void __launch_bounds__(256) head_softmax(
    const float* __restrict__ A, const float* __restrict__ We,
    const float* __restrict__ be, float* __restrict__ out)
{
    __shared__ float Ws[512 * 10];
    const int tid = threadIdx.x;
    for (int i = tid; i < 512 * 10; i += 256) Ws[i] = We[i];
    __syncthreads();
    const int lane = tid & 31, w = tid >> 5;
    const int row = blockIdx.x * 8 + w;

    float acc[10];
    #pragma unroll
    for (int c = 0; c < 10; c++) acc[c] = 0.0f;
    for (int k = lane; k < 512; k += 32) {
        float a = A[row * 512 + k];
        #pragma unroll
        for (int c = 0; c < 10; c++) acc[c] = fmaf(a, Ws[k * 10 + c], acc[c]);
    }
    #pragma unroll
    for (int c = 0; c < 10; c++) {
        #pragma unroll
        for (int o = 16; o > 0; o >>= 1)
            acc[c] += __shfl_xor_sync(0xffffffffu, acc[c], o);
    }
    if (lane == 0) {
        float v[10], mx = -1e30f;
        #pragma unroll
        for (int c = 0; c < 10; c++) { v[c] = acc[c] + be[c]; mx = fmaxf(mx, v[c]); }
        float s = 0.0f;
        #pragma unroll
        for (int c = 0; c < 10; c++) { v[c] = __expf(v[c] - mx); s += v[c]; }
        float inv = 1.0f / s;
        #pragma unroll
        for (int c = 0; c < 10; c++) out[row * 10 + c] = v[c] * inv;
    }
}

// ---------------------------------------------------------------------------
extern "C" void kernel_launch(void* const* d_in, const int* in_sizes, int n_in,
                              void* d_out, int out_size)
{
    const int*   src = (const int*)  d_in[0];
    const int*   dst = (const int*)  d_in[1];
    const float* W1  = (const float*)d_in[2];
    const float* b1  = (const float*)d_in[3];
    const float* W2  = (const float*)d_in[4];
    const float* b2  = (const float*)d_in[5];
    const float* Wa  = (const float*)d_in[6];
    const float* ba  = (const float*)d_in[7];
    const float* Wb  = (const float*)d_in[8];
    const float* bb  = (const float*)d_in[9];
    const float* Wc  = (const float*)d_in[10];
    const float* bc  = (const float*)d_in[11];
    const float* Wd  = (const float*)d_in[12];
    const float* bd  = (const float*)d_in[13];
    const float* We  = (const float*)d_in[14];
    const float* be  = (const float*)d_in[15];
    float* out = (float*)d_out;

    float *hg, *x1, *x2, *x3, *x4, *x4p;
    cudaGetSymbolAddress((void**)&hg,  g_hg);
    cudaGetSymbolAddress((void**)&x1,  g_x1);
    cudaGetSymbolAddress((void**)&x2,  g_x2);
    cudaGetSymbolAddress((void**)&x3,  g_x3);
    cudaGetSymbolAddress((void**)&x4,  g_x4);
    cudaGetSymbolAddress((void**)&x4p, g_x4p);

    const int SMEM = 113840;
    cudaFuncSetAttribute(gnn_kernel, cudaFuncAttributeMaxDynamicSharedMemorySize, SMEM);

    precompute_pwl<<<1, 512>>>(W1, b1, W2);
    gnn_kernel<<<NG, TPB, SMEM>>>(src, dst, b2, hg);

    gemm_mma<<<dim3(8, 8, 1),  256>>>(hg, 128,  Wa, ba, x1, 128,  512,  1, 0);
    gemm_mma<<<dim3(16, 8, 1), 256>>>(x1, 512,  Wb, bb, x2, 512,  1024, 1, 0);
    gemm_mma<<<dim3(16, 8, 1), 256>>>(x2, 1024, Wc, bc, x3, 1024, 1024, 1, 0);
    gemm_mma<<<dim3(8, 8, 2),  256>>>(x3, 1024, Wd, nullptr, x4p, 512, 512, 0, 512 * 512);
    combine_relu<<<(512 * 512 / 4 + 255) / 256, 256>>>(x4p, bd, x4, 512, 512 * 512 / 4);

    head_softmax<<<64, 256>>>(x4, We, be, out);
}

// round 6
// speedup vs baseline: 1.2001x; 1.1349x over previous
#include <cuda_runtime.h>
#include <cuda_bf16.h>

#define NG      512
#define NODES   200
#define EDGES   6400
#define HID     128
#define TPB     256

typedef __nv_bfloat16 bf16;

// ---- activation buffers (bf16 hi/lo pairs) --------------------------------
__device__ bf16 g_hgh[NG * HID],  g_hgl[NG * HID];
__device__ bf16 g_x1h[NG * 512],  g_x1l[NG * 512];
__device__ bf16 g_x2h[NG * 1024], g_x2l[NG * 1024];
__device__ bf16 g_x3h[NG * 1024], g_x3l[NG * 1024];
__device__ bf16 g_x4h[NG * 512],  g_x4l[NG * 512];

// ---- pre-converted transposed weights [N][K] bf16 hi/lo -------------------
__device__ bf16 g_wta_h[512 * 128],   g_wta_l[512 * 128];
__device__ bf16 g_wtb_h[1024 * 512],  g_wtb_l[1024 * 512];
__device__ bf16 g_wtc_h[1024 * 1024], g_wtc_l[1024 * 1024];
__device__ bf16 g_wtd_h[512 * 1024],  g_wtd_l[512 * 1024];

// ---- PWL tables for GNN t(a) ----------------------------------------------
__device__ float g_csorted[128];
__device__ float g_alpha[129 * 128];
__device__ float g_beta[129 * 128];

// ---- asm helpers -----------------------------------------------------------
__device__ __forceinline__ void cp16(void* smem, const void* gmem) {
    unsigned sa = (unsigned)__cvta_generic_to_shared(smem);
    asm volatile("cp.async.cg.shared.global [%0], [%1], 16;\n" :: "r"(sa), "l"(gmem));
}
__device__ __forceinline__ void cp_commit() {
    asm volatile("cp.async.commit_group;\n");
}
template <int N>
__device__ __forceinline__ void cp_wait() {
    asm volatile("cp.async.wait_group %0;\n" :: "n"(N));
}
__device__ __forceinline__ void ldsm4(unsigned r[4], const void* p) {
    unsigned a = (unsigned)__cvta_generic_to_shared(p);
    asm volatile("ldmatrix.sync.aligned.m8n8.x4.shared.b16 {%0,%1,%2,%3}, [%4];\n"
                 : "=r"(r[0]), "=r"(r[1]), "=r"(r[2]), "=r"(r[3]) : "r"(a));
}
__device__ __forceinline__ void mma_bf16(float c[4], const unsigned a[4],
                                         unsigned b0, unsigned b1) {
    asm volatile(
        "mma.sync.aligned.m16n8k16.row.col.f32.bf16.bf16.f32 "
        "{%0,%1,%2,%3}, {%4,%5,%6,%7}, {%8,%9}, {%0,%1,%2,%3};\n"
        : "+f"(c[0]), "+f"(c[1]), "+f"(c[2]), "+f"(c[3])
        : "r"(a[0]), "r"(a[1]), "r"(a[2]), "r"(a[3]), "r"(b0), "r"(b1));
}

// ---------------------------------------------------------------------------
// Weight convert: W [K][N] fp32 -> Wt_hi/lo [N][K] bf16. 32x32 tiles.
// ---------------------------------------------------------------------------
__global__ void __launch_bounds__(256) conv_w(
    const float* __restrict__ W, int K, int N,
    bf16* __restrict__ Oh, bf16* __restrict__ Ol)
{
    __shared__ float tile[32][33];
    const int c  = threadIdx.x & 31;
    const int r8 = threadIdx.x >> 5;
    const int nb = blockIdx.x * 32, kb = blockIdx.y * 32;
    #pragma unroll
    for (int j = 0; j < 4; j++)
        tile[r8 + j * 8][c] = W[(size_t)(kb + r8 + j * 8) * N + nb + c];
    __syncthreads();
    #pragma unroll
    for (int j = 0; j < 4; j++) {
        int n = nb + r8 + j * 8;
        float v = tile[c][r8 + j * 8];     // = W[kb + c][n]
        bf16 h = __float2bfloat16(v);
        Oh[(size_t)n * K + kb + c] = h;
        Ol[(size_t)n * K + kb + c] = __float2bfloat16(v - __bfloat162float(h));
    }
}

// ---------------------------------------------------------------------------
// Precompute PWL tables (unchanged since R3)
// ---------------------------------------------------------------------------
__global__ void __launch_bounds__(512) precompute_pwl(
    const float* __restrict__ W1, const float* __restrict__ b1,
    const float* __restrict__ W2)
{
    __shared__ float sc[128];
    __shared__ float sw[128], sb[128];
    __shared__ int   sidx[128];
    __shared__ float ssc[128];
    const int tid = threadIdx.x;

    if (tid < 128) {
        float w = W1[tid], b = b1[tid];
        sw[tid] = w; sb[tid] = b;
        sc[tid] = (w != 0.0f) ? (-b / w) : __int_as_float(0x7f800000);
    }
    __syncthreads();
    if (tid < 128) {
        float c = sc[tid];
        int r = 0;
        for (int j = 0; j < 128; j++) {
            float cj = sc[j];
            if (cj < c || (cj == c && j < tid)) r++;
        }
        sidx[r] = tid;
        ssc[r]  = c;
    }
    __syncthreads();
    if (tid < 128) g_csorted[tid] = ssc[tid];

    const int chunk = tid >> 7;
    const int j     = tid & 127;
    const int s0    = chunk * 32;

    float alpha = 0.0f, beta = 0.0f;
    for (int r = 0; r < 128; r++) {
        int k = sidx[r];
        float w = sw[k], b = sb[k];
        float W2kj = W2[k * 128 + j];
        if (w == 0.0f) { if (b > 0.0f) beta += b * W2kj; continue; }
        bool active = (w > 0.0f) ? (r < s0) : (r >= s0);
        if (active) { alpha = fmaf(w, W2kj, alpha); beta = fmaf(b, W2kj, beta); }
    }
    for (int s = s0; s < s0 + 32; s++) {
        g_alpha[s * 128 + j] = alpha;
        g_beta[s * 128 + j]  = beta;
        int k = sidx[s];
        float w = sw[k], b = sb[k];
        float W2kj = W2[k * 128 + j];
        float f = (w > 0.0f) ? 1.0f : ((w < 0.0f) ? -1.0f : 0.0f);
        alpha = fmaf(f * w, W2kj, alpha);
        beta  = fmaf(f * b, W2kj, beta);
    }
    if (chunk == 3) {
        g_alpha[128 * 128 + j] = alpha;
        g_beta[128 * 128 + j]  = beta;
    }
}

// ---------------------------------------------------------------------------
// Per-graph GNN kernel — R3 version, output written as bf16 hi/lo.
// ---------------------------------------------------------------------------
__global__ void __launch_bounds__(TPB, 2) gnn_kernel(
    const int*   __restrict__ src, const int*   __restrict__ dst,
    const float* __restrict__ b2,
    bf16* __restrict__ hgh, bf16* __restrict__ hgl)
{
    extern __shared__ float sf[];
    float* t    = sf;
    float* s_s  = sf + 25600;
    float* s_a  = s_s + NODES;
    float* s_ii = s_a + NODES;
    float* s_io = s_ii + NODES;
    int*   cnt  = (int*)(s_io + NODES);
    int*   cur  = cnt + 204;
    unsigned char* seg8 = (unsigned char*)(cur + 204);
    unsigned char* csr  = seg8 + 208;

    const int tid   = threadIdx.x;
    const int g     = blockIdx.x;
    const int ebase = g * EDGES;
    const int nbase = g * NODES;

    for (int i = tid; i < 204; i += TPB) { cnt[i] = 0; cur[i] = 0; }
    __syncthreads();
    for (int e = tid; e < EDGES; e += TPB) {
        int sl = src[ebase + e] - nbase;
        int dl = dst[ebase + e] - nbase;
        atomicAdd(&cnt[dl], 1);
        atomicAdd(&cur[sl], 1);
    }
    __syncthreads();
    for (int i = tid; i < NODES; i += TPB) {
        float idg = (float)cnt[i];
        float odg = (float)cur[i];
        float ii = rsqrtf(fmaxf(idg, 1.0f));
        float io = rsqrtf(fmaxf(odg, 1.0f));
        s_ii[i] = ii;
        s_io[i] = io;
        s_s[i]  = idg * io;
    }
    __syncthreads();
    if (tid < 32) {
        const int PER = 7;
        int base = tid * PER;
        int vals[PER];
        int s = 0;
        #pragma unroll
        for (int j = 0; j < PER; j++) {
            int i = base + j;
            int c = (i < NODES) ? cnt[i] : 0;
            vals[j] = c; s += c;
        }
        int pre = s;
        #pragma unroll
        for (int o = 1; o < 32; o <<= 1) {
            int tt = __shfl_up_sync(0xffffffffu, pre, o);
            if (tid >= o) pre += tt;
        }
        int run = pre - s;
        #pragma unroll
        for (int j = 0; j < PER; j++) {
            int i = base + j;
            if (i < NODES) { cnt[i] = run; cur[i] = run; run += vals[j]; }
        }
        if (tid == 31) cnt[NODES] = run;
    }
    __syncthreads();
    for (int e = tid; e < EDGES; e += TPB) {
        int sl = src[ebase + e] - nbase;
        int dl = dst[ebase + e] - nbase;
        int p  = atomicAdd(&cur[dl], 1);
        csr[p] = (unsigned char)sl;
    }
    __syncthreads();
    for (int d = tid; d < NODES; d += TPB) {
        float sum = 0.0f;
        int p0 = cnt[d], p1 = cnt[d + 1];
        for (int p = p0; p < p1; p++) sum += s_s[csr[p]];
        float a = sum * s_ii[d];
        s_a[d] = a;
        int lo = 0, hi = 128;
        while (lo < hi) {
            int m = (lo + hi) >> 1;
            if (g_csorted[m] < a) lo = m + 1; else hi = m;
        }
        seg8[d] = (unsigned char)lo;
    }
    __syncthreads();
    for (int idx = tid; idx < NODES * 32; idx += TPB) {
        int i = idx >> 5, q = idx & 31;
        float a  = s_a[i];
        float io = s_io[i];
        int   s  = seg8[i];
        float4 al = ((const float4*)(g_alpha + s * 128))[q];
        float4 be = ((const float4*)(g_beta  + s * 128))[q];
        float4 o;
        o.x = fmaf(al.x, a, be.x) * io;
        o.y = fmaf(al.y, a, be.y) * io;
        o.z = fmaf(al.z, a, be.z) * io;
        o.w = fmaf(al.w, a, be.w) * io;
        ((float4*)t)[idx] = o;
    }
    __syncthreads();
    const int tx = tid & 31;
    const int w  = tid >> 5;
    {
        float4 bb2 = ((const float4*)b2)[tx];
        float4 pacc = {0, 0, 0, 0};
        for (int d = w; d < NODES; d += 8) {
            int p0 = cnt[d], p1 = cnt[d + 1];
            float4 acc = {0, 0, 0, 0};
            for (int p = p0; p < p1; ++p) {
                int sv = csr[p];
                float4 v = ((const float4*)t)[sv * 32 + tx];
                acc.x += v.x; acc.y += v.y; acc.z += v.z; acc.w += v.w;
            }
            float ii = s_ii[d];
            pacc.x += fmaxf(fmaf(acc.x, ii, bb2.x), 0.0f);
            pacc.y += fmaxf(fmaf(acc.y, ii, bb2.y), 0.0f);
            pacc.z += fmaxf(fmaf(acc.z, ii, bb2.z), 0.0f);
            pacc.w += fmaxf(fmaf(acc.w, ii, bb2.w), 0.0f);
        }
        __syncthreads();
        ((float4*)t)[w * 32 + tx] = pacc;
    }
    __syncthreads();
    if (tid < HID) {
        float s = 0.0f;
        #pragma unroll
        for (int c = 0; c < 8; c++) s += t[c * HID + tid];
        float v = s * (1.0f / 200.0f);
        bf16 h = __float2bfloat16(v);
        hgh[g * HID + tid] = h;
        hgl[g * HID + tid] = __float2bfloat16(v - __bfloat162float(h));
    }
}

// ---------------------------------------------------------------------------
// bf16 hi/lo tensor-core GEMM, pre-converted operands:
//   out = relu( (Ah+Al) @ (Bh+Bl)^T + bias )  computed as Ah@Bh + Ah@Bl + Al@Bh
// A*: [M][K] bf16 row-major; B*: [N][K] bf16 (k-contiguous). Out: bf16 hi/lo.
// CTA 256 thr, 64x64 tile, warps 2(m) x 4(n), warp tile 32x16, ktile=32,
// cp.async double-buffered, ldmatrix fragments.
// ---------------------------------------------------------------------------
#define TSB 40   // SMEM row stride in bf16 (80 B): ldmatrix conflict-free

__global__ void __launch_bounds__(256) gemm_bf16(
    const bf16* __restrict__ Ah, const bf16* __restrict__ Al,
    const bf16* __restrict__ Bh, const bf16* __restrict__ Bl,
    const float* __restrict__ bias,
    bf16* __restrict__ Oh, bf16* __restrict__ Ol,
    int K, int Nc)
{
    __shared__ bf16 sAh[2][64 * TSB], sAl[2][64 * TSB];
    __shared__ bf16 sBh[2][64 * TSB], sBl[2][64 * TSB];

    const int tid  = threadIdx.x;
    const int lane = tid & 31;
    const int wid  = tid >> 5;
    const int wm   = wid & 1;          // 2 m-groups of 32 rows
    const int wn   = wid >> 1;         // 4 n-groups of 16 cols
    const int row0 = blockIdx.y * 64, col0 = blockIdx.x * 64;

    // loader coords: 128 threads per (hi|lo) plane, 2 chunks each per array
    const int th  = tid & 127;
    const int lr  = th >> 2;           // 0..31 (rows r and r+32)
    const int lc  = (th & 3) * 8;      // bf16 col offset within 32-k tile
    const bool pl = (tid < 128);       // true -> hi plane, false -> lo plane

    const bf16* gA = (pl ? Ah : Al) + (size_t)(row0 + lr) * K + lc;
    const bf16* gB = (pl ? Bh : Bl) + (size_t)(col0 + lr) * K + lc;
    bf16* dA0 = (pl ? sAh[0] : sAl[0]) + lr * TSB + lc;
    bf16* dB0 = (pl ? sBh[0] : sBl[0]) + lr * TSB + lc;
    bf16* dA1 = (pl ? sAh[1] : sAl[1]) + lr * TSB + lc;
    bf16* dB1 = (pl ? sBh[1] : sBl[1]) + lr * TSB + lc;

    float c[2][2][4];
    #pragma unroll
    for (int mi = 0; mi < 2; mi++)
        #pragma unroll
        for (int ni = 0; ni < 2; ni++)
            #pragma unroll
            for (int q = 0; q < 4; q++) c[mi][ni][q] = 0.0f;

    // prologue: stage 0
    cp16(dA0, gA);                cp16(dA0 + 32 * TSB, gA + (size_t)32 * K);
    cp16(dB0, gB);                cp16(dB0 + 32 * TSB, gB + (size_t)32 * K);
    cp_commit();

    const int nkt = K >> 5;
    const int frow = lane & 15;
    const int fk   = (lane >> 4) * 8;
    int buf = 0;

    for (int kt = 0; kt < nkt; kt++) {
        if (kt + 1 < nkt) {
            const bf16* gA1 = gA + (size_t)(kt + 1) * 32;
            const bf16* gB1 = gB + (size_t)(kt + 1) * 32;
            bf16* dA = buf ? dA0 : dA1;
            bf16* dB = buf ? dB0 : dB1;
            cp16(dA, gA1); cp16(dA + 32 * TSB, gA1 + (size_t)32 * K);
            cp16(dB, gB1); cp16(dB + 32 * TSB, gB1 + (size_t)32 * K);
            cp_commit();
            cp_wait<1>();
        } else {
            cp_wait<0>();
        }
        __syncthreads();

        #pragma unroll
        for (int ks = 0; ks < 32; ks += 16) {
            unsigned ah[2][4], al[2][4], bh[4], bl[4];
            #pragma unroll
            for (int mi = 0; mi < 2; mi++) {
                int ro = (wm * 32 + mi * 16 + frow) * TSB + ks + fk;
                ldsm4(ah[mi], &sAh[buf][ro]);
                ldsm4(al[mi], &sAl[buf][ro]);
            }
            {
                int no = (wn * 16 + frow) * TSB + ks + fk;
                ldsm4(bh, &sBh[buf][no]);
                ldsm4(bl, &sBl[buf][no]);
            }
            #pragma unroll
            for (int mi = 0; mi < 2; mi++)
                #pragma unroll
                for (int ni = 0; ni < 2; ni++) {
                    unsigned b0h = ni ? bh[1] : bh[0], b1h = ni ? bh[3] : bh[2];
                    unsigned b0l = ni ? bl[1] : bl[0], b1l = ni ? bl[3] : bl[2];
                    mma_bf16(c[mi][ni], ah[mi], b0h, b1h);
                    mma_bf16(c[mi][ni], ah[mi], b0l, b1l);
                    mma_bf16(c[mi][ni], al[mi], b0h, b1h);
                }
        }
        __syncthreads();
        buf ^= 1;
    }

    // epilogue: bias + relu, write bf16 hi/lo pairs
    const int g  = lane >> 2;
    const int tg = lane & 3;
    #pragma unroll
    for (int mi = 0; mi < 2; mi++) {
        #pragma unroll
        for (int ni = 0; ni < 2; ni++) {
            int r  = row0 + wm * 32 + mi * 16 + g;
            int cc = col0 + wn * 16 + ni * 8 + tg * 2;
            float2 bv = *(const float2*)(bias + cc);
            #pragma unroll
            for (int half = 0; half < 2; half++) {
                int rr = r + half * 8;
                float vx = fmaxf(c[mi][ni][half * 2 + 0] + bv.x, 0.0f);
                float vy = fmaxf(c[mi][ni][half * 2 + 1] + bv.y, 0.0f);
                bf16 hx = __float2bfloat16(vx);
                bf16 hy = __float2bfloat16(vy);
                __nv_bfloat162 hp(hx, hy);
                __nv_bfloat162 lp(__float2bfloat16(vx - __bfloat162float(hx)),
                                  __float2bfloat16(vy - __bfloat162float(hy)));
                *(__nv_bfloat162*)(Oh + (size_t)rr * Nc + cc) = hp;
                *(__nv_bfloat162*)(Ol + (size_t)rr * Nc + cc) = lp;
            }
        }
    }
}

// ---------------------------------------------------------------------------
// Final layer: out = softmax((x4h+x4l) @ We + be). Warp per row.
// ---------------------------------------------------------------------------
__global__ void __launch_bounds__(256) head_softmax(
    const bf16* __restrict__ Ah, const bf16* __restrict__ Al,
    const float* __restrict__ We, const float* __restrict__ be,
    float* __restrict__ out)
{
    __shared__ float Ws[512 * 10];
    const int tid = threadIdx.x;
    for (int i = tid; i < 512 * 10; i += 256) Ws[i] = We[i];
    __syncthreads();
    const int lane = tid & 31, w = tid >> 5;
    const int row = blockIdx.x * 8 + w;

    float acc[10];
    #pragma unroll
    for (int c = 0; c < 10; c++) acc[c] = 0.0f;
    for (int k = lane; k < 512; k += 32) {
        float a = __bfloat162float(Ah[row * 512 + k]) +
                  __bfloat162float(Al[row * 512 + k]);
        #pragma unroll
        for (int c = 0; c < 10; c++) acc[c] = fmaf(a, Ws[k * 10 + c], acc[c]);
    }
    #pragma unroll
    for (int c = 0; c < 10; c++) {
        #pragma unroll
        for (int o = 16; o > 0; o >>= 1)
            acc[c] += __shfl_xor_sync(0xffffffffu, acc[c], o);
    }
    if (lane == 0) {
        float v[10], mx = -1e30f;
        #pragma unroll
        for (int c = 0; c < 10; c++) { v[c] = acc[c] + be[c]; mx = fmaxf(mx, v[c]); }
        float s = 0.0f;
        #pragma unroll
        for (int c = 0; c < 10; c++) { v[c] = __expf(v[c] - mx); s += v[c]; }
        float inv = 1.0f / s;
        #pragma unroll
        for (int c = 0; c < 10; c++) out[row * 10 + c] = v[c] * inv;
    }
}

// ---------------------------------------------------------------------------
extern "C" void kernel_launch(void* const* d_in, const int* in_sizes, int n_in,
                              void* d_out, int out_size)
{
    const int*   src = (const int*)  d_in[0];
    const int*   dst = (const int*)  d_in[1];
    const float* W1  = (const float*)d_in[2];
    const float* b1  = (const float*)d_in[3];
    const float* W2  = (const float*)d_in[4];
    const float* b2  = (const float*)d_in[5];
    const float* Wa  = (const float*)d_in[6];
    const float* ba  = (const float*)d_in[7];
    const float* Wb  = (const float*)d_in[8];
    const float* bb  = (const float*)d_in[9];
    const float* Wc  = (const float*)d_in[10];
    const float* bc  = (const float*)d_in[11];
    const float* Wd  = (const float*)d_in[12];
    const float* bd  = (const float*)d_in[13];
    const float* We  = (const float*)d_in[14];
    const float* be  = (const float*)d_in[15];
    float* out = (float*)d_out;

    bf16 *hgh, *hgl, *x1h, *x1l, *x2h, *x2l, *x3h, *x3l, *x4h, *x4l;
    bf16 *wah, *wal, *wbh, *wbl, *wch, *wcl, *wdh, *wdl;
    cudaGetSymbolAddress((void**)&hgh, g_hgh); cudaGetSymbolAddress((void**)&hgl, g_hgl);
    cudaGetSymbolAddress((void**)&x1h, g_x1h); cudaGetSymbolAddress((void**)&x1l, g_x1l);
    cudaGetSymbolAddress((void**)&x2h, g_x2h); cudaGetSymbolAddress((void**)&x2l, g_x2l);
    cudaGetSymbolAddress((void**)&x3h, g_x3h); cudaGetSymbolAddress((void**)&x3l, g_x3l);
    cudaGetSymbolAddress((void**)&x4h, g_x4h); cudaGetSymbolAddress((void**)&x4l, g_x4l);
    cudaGetSymbolAddress((void**)&wah, g_wta_h); cudaGetSymbolAddress((void**)&wal, g_wta_l);
    cudaGetSymbolAddress((void**)&wbh, g_wtb_h); cudaGetSymbolAddress((void**)&wbl, g_wtb_l);
    cudaGetSymbolAddress((void**)&wch, g_wtc_h); cudaGetSymbolAddress((void**)&wcl, g_wtc_l);
    cudaGetSymbolAddress((void**)&wdh, g_wtd_h); cudaGetSymbolAddress((void**)&wdl, g_wtd_l);

    const int SMEM = 113840;
    cudaFuncSetAttribute(gnn_kernel, cudaFuncAttributeMaxDynamicSharedMemorySize, SMEM);

    // weight converts (W [K][N] -> Wt [N][K] hi/lo)
    conv_w<<<dim3(512 / 32,  128 / 32),  256>>>(Wa, 128,  512,  wah, wal);
    conv_w<<<dim3(1024 / 32, 512 / 32),  256>>>(Wb, 512,  1024, wbh, wbl);
    conv_w<<<dim3(1024 / 32, 1024 / 32), 256>>>(Wc, 1024, 1024, wch, wcl);
    conv_w<<<dim3(512 / 32,  1024 / 32), 256>>>(Wd, 1024, 512,  wdh, wdl);

    precompute_pwl<<<1, 512>>>(W1, b1, W2);
    gnn_kernel<<<NG, TPB, SMEM>>>(src, dst, b2, hgh, hgl);

    gemm_bf16<<<dim3(512 / 64,  8), 256>>>(hgh, hgl, wah, wal, ba, x1h, x1l, 128,  512);
    gemm_bf16<<<dim3(1024 / 64, 8), 256>>>(x1h, x1l, wbh, wbl, bb, x2h, x2l, 512,  1024);
    gemm_bf16<<<dim3(1024 / 64, 8), 256>>>(x2h, x2l, wch, wcl, bc, x3h, x3l, 1024, 1024);
    gemm_bf16<<<dim3(512 / 64,  8), 256>>>(x3h, x3l, wdh, wdl, bd, x4h, x4l, 1024, 512);

    head_softmax<<<64, 256>>>(x4h, x4l, We, be, out);
}

// round 7
// speedup vs baseline: 1.2905x; 1.0753x over previous
#include <cuda_runtime.h>
#include <cuda_bf16.h>

#define NG      512
#define NODES   200
#define EDGES   6400
#define HID     128

typedef __nv_bfloat16 bf16;

// ---- activation buffers (bf16 hi/lo pairs) --------------------------------
__device__ bf16 g_hgh[NG * HID],  g_hgl[NG * HID];
__device__ bf16 g_x1h[NG * 512],  g_x1l[NG * 512];
__device__ bf16 g_x2h[NG * 1024], g_x2l[NG * 1024];
__device__ bf16 g_x3h[NG * 1024], g_x3l[NG * 1024];
__device__ bf16 g_x4h[NG * 512],  g_x4l[NG * 512];

// ---- pre-converted transposed weights [N][K] bf16 hi/lo -------------------
__device__ bf16 g_wta_h[512 * 128],   g_wta_l[512 * 128];
__device__ bf16 g_wtb_h[1024 * 512],  g_wtb_l[1024 * 512];
__device__ bf16 g_wtc_h[1024 * 1024], g_wtc_l[1024 * 1024];
__device__ bf16 g_wtd_h[512 * 1024],  g_wtd_l[512 * 1024];

// ---- PWL tables for GNN t(a) ----------------------------------------------
__device__ float g_csorted[128];
__device__ float g_alpha[129 * 128];
__device__ float g_beta[129 * 128];

// ---- asm helpers -----------------------------------------------------------
__device__ __forceinline__ void cp16(void* smem, const void* gmem) {
    unsigned sa = (unsigned)__cvta_generic_to_shared(smem);
    asm volatile("cp.async.cg.shared.global [%0], [%1], 16;\n" :: "r"(sa), "l"(gmem));
}
__device__ __forceinline__ void cp_commit() {
    asm volatile("cp.async.commit_group;\n");
}
template <int N>
__device__ __forceinline__ void cp_wait() {
    asm volatile("cp.async.wait_group %0;\n" :: "n"(N));
}
__device__ __forceinline__ void ldsm4(unsigned r[4], const void* p) {
    unsigned a = (unsigned)__cvta_generic_to_shared(p);
    asm volatile("ldmatrix.sync.aligned.m8n8.x4.shared.b16 {%0,%1,%2,%3}, [%4];\n"
                 : "=r"(r[0]), "=r"(r[1]), "=r"(r[2]), "=r"(r[3]) : "r"(a));
}
__device__ __forceinline__ void ldsm4t(unsigned r[4], const void* p) {
    unsigned a = (unsigned)__cvta_generic_to_shared(p);
    asm volatile("ldmatrix.sync.aligned.m8n8.x4.trans.shared.b16 {%0,%1,%2,%3}, [%4];\n"
                 : "=r"(r[0]), "=r"(r[1]), "=r"(r[2]), "=r"(r[3]) : "r"(a));
}
__device__ __forceinline__ void mma_bf16(float c[4], const unsigned a[4],
                                         unsigned b0, unsigned b1) {
    asm volatile(
        "mma.sync.aligned.m16n8k16.row.col.f32.bf16.bf16.f32 "
        "{%0,%1,%2,%3}, {%4,%5,%6,%7}, {%8,%9}, {%0,%1,%2,%3};\n"
        : "+f"(c[0]), "+f"(c[1]), "+f"(c[2]), "+f"(c[3])
        : "r"(a[0]), "r"(a[1]), "r"(a[2]), "r"(a[3]), "r"(b0), "r"(b1));
}

// ---------------------------------------------------------------------------
// Weight convert: W [K][N] fp32 -> Wt_hi/lo [N][K] bf16. 32x32 tiles.
// ---------------------------------------------------------------------------
__global__ void __launch_bounds__(256) conv_w(
    const float* __restrict__ W, int K, int N,
    bf16* __restrict__ Oh, bf16* __restrict__ Ol)
{
    __shared__ float tile[32][33];
    const int c  = threadIdx.x & 31;
    const int r8 = threadIdx.x >> 5;
    const int nb = blockIdx.x * 32, kb = blockIdx.y * 32;
    #pragma unroll
    for (int j = 0; j < 4; j++)
        tile[r8 + j * 8][c] = W[(size_t)(kb + r8 + j * 8) * N + nb + c];
    __syncthreads();
    #pragma unroll
    for (int j = 0; j < 4; j++) {
        int n = nb + r8 + j * 8;
        float v = tile[c][r8 + j * 8];
        bf16 h = __float2bfloat16(v);
        Oh[(size_t)n * K + kb + c] = h;
        Ol[(size_t)n * K + kb + c] = __float2bfloat16(v - __bfloat162float(h));
    }
}

// ---------------------------------------------------------------------------
// Precompute PWL tables (unchanged since R3)
// ---------------------------------------------------------------------------
__global__ void __launch_bounds__(512) precompute_pwl(
    const float* __restrict__ W1, const float* __restrict__ b1,
    const float* __restrict__ W2)
{
    __shared__ float sc[128];
    __shared__ float sw[128], sb[128];
    __shared__ int   sidx[128];
    __shared__ float ssc[128];
    const int tid = threadIdx.x;

    if (tid < 128) {
        float w = W1[tid], b = b1[tid];
        sw[tid] = w; sb[tid] = b;
        sc[tid] = (w != 0.0f) ? (-b / w) : __int_as_float(0x7f800000);
    }
    __syncthreads();
    if (tid < 128) {
        float c = sc[tid];
        int r = 0;
        for (int j = 0; j < 128; j++) {
            float cj = sc[j];
            if (cj < c || (cj == c && j < tid)) r++;
        }
        sidx[r] = tid;
        ssc[r]  = c;
    }
    __syncthreads();
    if (tid < 128) g_csorted[tid] = ssc[tid];

    const int chunk = tid >> 7;
    const int j     = tid & 127;
    const int s0    = chunk * 32;

    float alpha = 0.0f, beta = 0.0f;
    for (int r = 0; r < 128; r++) {
        int k = sidx[r];
        float w = sw[k], b = sb[k];
        float W2kj = W2[k * 128 + j];
        if (w == 0.0f) { if (b > 0.0f) beta += b * W2kj; continue; }
        bool active = (w > 0.0f) ? (r < s0) : (r >= s0);
        if (active) { alpha = fmaf(w, W2kj, alpha); beta = fmaf(b, W2kj, beta); }
    }
    for (int s = s0; s < s0 + 32; s++) {
        g_alpha[s * 128 + j] = alpha;
        g_beta[s * 128 + j]  = beta;
        int k = sidx[s];
        float w = sw[k], b = sb[k];
        float W2kj = W2[k * 128 + j];
        float f = (w > 0.0f) ? 1.0f : ((w < 0.0f) ? -1.0f : 0.0f);
        alpha = fmaf(f * w, W2kj, alpha);
        beta  = fmaf(f * b, W2kj, beta);
    }
    if (chunk == 3) {
        g_alpha[128 * 128 + j] = alpha;
        g_beta[128 * 128 + j]  = beta;
    }
}

// ---------------------------------------------------------------------------
// GNN kernel v2: dense count-matrix + tensor-core SpMM. 512 threads/graph.
// C: bf16[224][216] (M pad 224, K pad 216, exact counts)
// th/tl: bf16[208][136] = t hi/lo in [s][j] layout (K pad rows zeroed)
// h2 = relu(ii .* (C @ (th+tl)) + b2); hg = mean pool, fused in epilogue.
// SMEM = 214,752 B.
// ---------------------------------------------------------------------------
#define CS 216   // C row stride (bf16): 108 words == 12 mod 32, conflict-free
#define TSN 136  // t row stride (bf16): 68 words == 4 mod 32, conflict-free

__global__ void __launch_bounds__(512, 1) gnn_kernel(
    const int*   __restrict__ src, const int*   __restrict__ dst,
    const float* __restrict__ b2,
    bf16* __restrict__ hgh, bf16* __restrict__ hgl)
{
    extern __shared__ unsigned char smraw[];
    bf16*  C    = (bf16*)smraw;                     // 224*216
    bf16*  th   = C + 224 * CS;                     // 208*136
    bf16*  tl   = th + 208 * TSN;                   // 208*136
    float* s_a  = (float*)(tl + 208 * TSN);         // 224
    float* s_ii = s_a + 224;
    float* s_io = s_ii + 224;
    float* s_s  = s_io + 224;
    float* pool = s_s + 224;                        // 256
    unsigned char* seg = (unsigned char*)(pool + 256); // 224

    const int tid   = threadIdx.x;
    const int g     = blockIdx.x;
    const int ebase = g * EDGES;
    const int nbase = g * NODES;

    // --- 1. zero C fully; zero t pad rows (s = 200..207) ---
    {
        uint4 z = {0, 0, 0, 0};
        uint4* C4 = (uint4*)C;                      // 6048 uint4
        for (int i = tid; i < 224 * CS * 2 / 16; i += 512) C4[i] = z;
        uint4* tp = (uint4*)(th + 200 * TSN);       // 136 uint4
        uint4* lp = (uint4*)(tl + 200 * TSN);
        for (int i = tid; i < 8 * TSN * 2 / 16; i += 512) { tp[i] = z; lp[i] = z; }
    }
    __syncthreads();

    // --- 2. build count matrix: one bf16x2 atomic per edge ---
    {
        const bf16 one = __float2bfloat16(1.0f);
        const bf16 zer = __float2bfloat16(0.0f);
        __nv_bfloat162 v10 = __halves2bfloat162(one, zer);
        __nv_bfloat162 v01 = __halves2bfloat162(zer, one);
        __nv_bfloat162* C2 = (__nv_bfloat162*)C;    // row stride 108 words
        for (int e = tid; e < EDGES; e += 512) {
            int sl = src[ebase + e] - nbase;
            int dl = dst[ebase + e] - nbase;
            atomicAdd(&C2[dl * (CS / 2) + (sl >> 1)], (sl & 1) ? v01 : v10);
        }
    }
    __syncthreads();

    // --- 3. row sums -> in_deg (s_a), inv_in (s_ii) ---
    if (tid < 224) {
        const __nv_bfloat162* row = (const __nv_bfloat162*)C + tid * (CS / 2);
        float sum = 0.0f;
        for (int w = 0; w < CS / 2; w++) {
            float2 f = __bfloat1622float2(row[w]);
            sum += f.x + f.y;
        }
        s_a[tid]  = sum;
        s_ii[tid] = rsqrtf(fmaxf(sum, 1.0f));
    }
    __syncthreads();

    // --- 4. col sums -> out_deg, inv_out (s_io), s_s = in_deg*inv_out ---
    if (tid < CS) {
        float sum = 0.0f;
        for (int d = 0; d < NODES; d++) sum += __bfloat162float(C[d * CS + tid]);
        float io = rsqrtf(fmaxf(sum, 1.0f));
        s_io[tid] = io;
        s_s[tid]  = s_a[tid] * io;
    }
    __syncthreads();

    // --- 5. layer-1 agg: a[d] = (C[d,:] . s_s) * ii[d]; segment search ---
    if (tid < NODES) {
        const __nv_bfloat162* row = (const __nv_bfloat162*)C + tid * (CS / 2);
        const float2* ss2 = (const float2*)s_s;
        float sum = 0.0f;
        for (int w = 0; w < CS / 2; w++) {
            float2 f = __bfloat1622float2(row[w]);
            float2 s = ss2[w];
            sum = fmaf(f.x, s.x, fmaf(f.y, s.y, sum));
        }
        float a = sum * s_ii[tid];
        s_a[tid] = a;
        int lo = 0, hi = 128;
        while (lo < hi) {
            int m = (lo + hi) >> 1;
            if (g_csorted[m] < a) lo = m + 1; else hi = m;
        }
        seg[tid] = (unsigned char)lo;
    }
    __syncthreads();

    // --- 6. produce t hi/lo in [s][j] layout ---
    for (int idx = tid; idx < NODES * 32; idx += 512) {
        int i = idx >> 5, q = idx & 31;
        float a  = s_a[i];
        float io = s_io[i];
        int   s  = seg[i];
        float4 al = ((const float4*)(g_alpha + s * 128))[q];
        float4 be = ((const float4*)(g_beta  + s * 128))[q];
        float v0 = fmaf(al.x, a, be.x) * io;
        float v1 = fmaf(al.y, a, be.y) * io;
        float v2 = fmaf(al.z, a, be.z) * io;
        float v3 = fmaf(al.w, a, be.w) * io;
        bf16 h0 = __float2bfloat16(v0), h1 = __float2bfloat16(v1);
        bf16 h2 = __float2bfloat16(v2), h3 = __float2bfloat16(v3);
        __nv_bfloat162 hp0 = __halves2bfloat162(h0, h1);
        __nv_bfloat162 hp1 = __halves2bfloat162(h2, h3);
        __nv_bfloat162 lp0 = __halves2bfloat162(
            __float2bfloat16(v0 - __bfloat162float(h0)),
            __float2bfloat16(v1 - __bfloat162float(h1)));
        __nv_bfloat162 lp1 = __halves2bfloat162(
            __float2bfloat16(v2 - __bfloat162float(h2)),
            __float2bfloat16(v3 - __bfloat162float(h3)));
        __nv_bfloat162* dh = (__nv_bfloat162*)(th + i * TSN + q * 4);
        __nv_bfloat162* dl = (__nv_bfloat162*)(tl + i * TSN + q * 4);
        dh[0] = hp0; dh[1] = hp1;
        dl[0] = lp0; dl[1] = lp1;
    }
    __syncthreads();

    // --- 7. MMA: acc[224x128] = C @ (th + tl) ---
    const int lane = tid & 31;
    const int wid  = tid >> 5;        // 16 warps
    const int wm   = wid & 1;         // 2 m-groups x 112 rows (7 m16)
    const int wn   = wid >> 1;        // 8 n-groups x 16 cols (2 n8)

    float c[7][2][4];
    #pragma unroll
    for (int mi = 0; mi < 7; mi++)
        #pragma unroll
        for (int ni = 0; ni < 2; ni++)
            #pragma unroll
            for (int q = 0; q < 4; q++) c[mi][ni][q] = 0.0f;

    // fragment addressing
    const int aRow = wm * 112 + (lane & 15);        // + mi*16
    const int aCol = ((lane >> 4) & 1) * 8;         // + kt*16
    const int bRow = (lane & 7) + ((lane >> 4) & 1) * 8;  // + kt*16 (k)
    const int bCol = wn * 16 + ((lane >> 3) & 1) * 8;     // n

    for (int kt = 0; kt < 13; kt++) {
        unsigned bh[4], bl[4];
        const int kr = kt * 16 + bRow;
        ldsm4t(bh, th + kr * TSN + bCol);
        ldsm4t(bl, tl + kr * TSN + bCol);
        #pragma unroll
        for (int mi = 0; mi < 7; mi++) {
            unsigned af[4];
            ldsm4(af, C + (aRow + mi * 16) * CS + kt * 16 + aCol);
            mma_bf16(c[mi][0], af, bh[0], bh[2]);
            mma_bf16(c[mi][0], af, bl[0], bl[2]);
            mma_bf16(c[mi][1], af, bh[1], bh[3]);
            mma_bf16(c[mi][1], af, bl[1], bl[3]);
        }
    }

    // --- 8. epilogue: h2 = relu(acc*ii + b2), fused mean pool ---
    {
        const int gg = lane >> 2;
        const int tg = lane & 3;
        float bx[2], by[2];
        #pragma unroll
        for (int ni = 0; ni < 2; ni++) {
            int col = wn * 16 + ni * 8 + tg * 2;
            float2 bv = *(const float2*)(b2 + col);
            bx[ni] = bv.x; by[ni] = bv.y;
        }
        float ps[2][2] = {{0, 0}, {0, 0}};
        #pragma unroll
        for (int mi = 0; mi < 7; mi++) {
            int r0 = wm * 112 + mi * 16 + gg;
            int r1 = r0 + 8;
            float ii0 = (r0 < NODES) ? s_ii[r0] : 0.0f;
            float ii1 = (r1 < NODES) ? s_ii[r1] : 0.0f;
            #pragma unroll
            for (int ni = 0; ni < 2; ni++) {
                if (r0 < NODES) {
                    ps[ni][0] += fmaxf(fmaf(c[mi][ni][0], ii0, bx[ni]), 0.0f);
                    ps[ni][1] += fmaxf(fmaf(c[mi][ni][1], ii0, by[ni]), 0.0f);
                }
                if (r1 < NODES) {
                    ps[ni][0] += fmaxf(fmaf(c[mi][ni][2], ii1, bx[ni]), 0.0f);
                    ps[ni][1] += fmaxf(fmaf(c[mi][ni][3], ii1, by[ni]), 0.0f);
                }
            }
        }
        // reduce over gg (lanes with same tg)
        #pragma unroll
        for (int off = 16; off >= 4; off >>= 1) {
            #pragma unroll
            for (int ni = 0; ni < 2; ni++) {
                ps[ni][0] += __shfl_down_sync(0xffffffffu, ps[ni][0], off);
                ps[ni][1] += __shfl_down_sync(0xffffffffu, ps[ni][1], off);
            }
        }
        if (lane < 4) {
            #pragma unroll
            for (int ni = 0; ni < 2; ni++) {
                int col = wn * 16 + ni * 8 + lane * 2;
                pool[wm * 128 + col]     = ps[ni][0];
                pool[wm * 128 + col + 1] = ps[ni][1];
            }
        }
    }
    __syncthreads();
    if (tid < HID) {
        float v = (pool[tid] + pool[128 + tid]) * (1.0f / 200.0f);
        bf16 h = __float2bfloat16(v);
        hgh[g * HID + tid] = h;
        hgl[g * HID + tid] = __float2bfloat16(v - __bfloat162float(h));
    }
}

// ---------------------------------------------------------------------------
// bf16 hi/lo tensor-core GEMM (unchanged from R6, working).
// ---------------------------------------------------------------------------
#define TSB 40

__global__ void __launch_bounds__(256) gemm_bf16(
    const bf16* __restrict__ Ah, const bf16* __restrict__ Al,
    const bf16* __restrict__ Bh, const bf16* __restrict__ Bl,
    const float* __restrict__ bias,
    bf16* __restrict__ Oh, bf16* __restrict__ Ol,
    int K, int Nc)
{
    __shared__ bf16 sAh[2][64 * TSB], sAl[2][64 * TSB];
    __shared__ bf16 sBh[2][64 * TSB], sBl[2][64 * TSB];

    const int tid  = threadIdx.x;
    const int lane = tid & 31;
    const int wid  = tid >> 5;
    const int wm   = wid & 1;
    const int wn   = wid >> 1;
    const int row0 = blockIdx.y * 64, col0 = blockIdx.x * 64;

    const int th  = tid & 127;
    const int lr  = th >> 2;
    const int lc  = (th & 3) * 8;
    const bool pl = (tid < 128);

    const bf16* gA = (pl ? Ah : Al) + (size_t)(row0 + lr) * K + lc;
    const bf16* gB = (pl ? Bh : Bl) + (size_t)(col0 + lr) * K + lc;
    bf16* dA0 = (pl ? sAh[0] : sAl[0]) + lr * TSB + lc;
    bf16* dB0 = (pl ? sBh[0] : sBl[0]) + lr * TSB + lc;
    bf16* dA1 = (pl ? sAh[1] : sAl[1]) + lr * TSB + lc;
    bf16* dB1 = (pl ? sBh[1] : sBl[1]) + lr * TSB + lc;

    float c[2][2][4];
    #pragma unroll
    for (int mi = 0; mi < 2; mi++)
        #pragma unroll
        for (int ni = 0; ni < 2; ni++)
            #pragma unroll
            for (int q = 0; q < 4; q++) c[mi][ni][q] = 0.0f;

    cp16(dA0, gA);                cp16(dA0 + 32 * TSB, gA + (size_t)32 * K);
    cp16(dB0, gB);                cp16(dB0 + 32 * TSB, gB + (size_t)32 * K);
    cp_commit();

    const int nkt = K >> 5;
    const int frow = lane & 15;
    const int fk   = (lane >> 4) * 8;
    int buf = 0;

    for (int kt = 0; kt < nkt; kt++) {
        if (kt + 1 < nkt) {
            const bf16* gA1 = gA + (size_t)(kt + 1) * 32;
            const bf16* gB1 = gB + (size_t)(kt + 1) * 32;
            bf16* dA = buf ? dA0 : dA1;
            bf16* dB = buf ? dB0 : dB1;
            cp16(dA, gA1); cp16(dA + 32 * TSB, gA1 + (size_t)32 * K);
            cp16(dB, gB1); cp16(dB + 32 * TSB, gB1 + (size_t)32 * K);
            cp_commit();
            cp_wait<1>();
        } else {
            cp_wait<0>();
        }
        __syncthreads();

        #pragma unroll
        for (int ks = 0; ks < 32; ks += 16) {
            unsigned ah[2][4], al[2][4], bh[4], bl[4];
            #pragma unroll
            for (int mi = 0; mi < 2; mi++) {
                int ro = (wm * 32 + mi * 16 + frow) * TSB + ks + fk;
                ldsm4(ah[mi], &sAh[buf][ro]);
                ldsm4(al[mi], &sAl[buf][ro]);
            }
            {
                int no = (wn * 16 + frow) * TSB + ks + fk;
                ldsm4(bh, &sBh[buf][no]);
                ldsm4(bl, &sBl[buf][no]);
            }
            #pragma unroll
            for (int mi = 0; mi < 2; mi++)
                #pragma unroll
                for (int ni = 0; ni < 2; ni++) {
                    unsigned b0h = ni ? bh[1] : bh[0], b1h = ni ? bh[3] : bh[2];
                    unsigned b0l = ni ? bl[1] : bl[0], b1l = ni ? bl[3] : bl[2];
                    mma_bf16(c[mi][ni], ah[mi], b0h, b1h);
                    mma_bf16(c[mi][ni], ah[mi], b0l, b1l);
                    mma_bf16(c[mi][ni], al[mi], b0h, b1h);
                }
        }
        __syncthreads();
        buf ^= 1;
    }

    const int g  = lane >> 2;
    const int tg = lane & 3;
    #pragma unroll
    for (int mi = 0; mi < 2; mi++) {
        #pragma unroll
        for (int ni = 0; ni < 2; ni++) {
            int r  = row0 + wm * 32 + mi * 16 + g;
            int cc = col0 + wn * 16 + ni * 8 + tg * 2;
            float2 bv = *(const float2*)(bias + cc);
            #pragma unroll
            for (int half = 0; half < 2; half++) {
                int rr = r + half * 8;
                float vx = fmaxf(c[mi][ni][half * 2 + 0] + bv.x, 0.0f);
                float vy = fmaxf(c[mi][ni][half * 2 + 1] + bv.y, 0.0f);
                bf16 hx = __float2bfloat16(vx);
                bf16 hy = __float2bfloat16(vy);
                __nv_bfloat162 hp(hx, hy);
                __nv_bfloat162 lp(__float2bfloat16(vx - __bfloat162float(hx)),
                                  __float2bfloat16(vy - __bfloat162float(hy)));
                *(__nv_bfloat162*)(Oh + (size_t)rr * Nc + cc) = hp;
                *(__nv_bfloat162*)(Ol + (size_t)rr * Nc + cc) = lp;
            }
        }
    }
}

// ---------------------------------------------------------------------------
// Final layer: out = softmax((x4h+x4l) @ We + be). Warp per row.
// ---------------------------------------------------------------------------
__global__ void __launch_bounds__(256) head_softmax(
    const bf16* __restrict__ Ah, const bf16* __restrict__ Al,
    const float* __restrict__ We, const float* __restrict__ be,
    float* __restrict__ out)
{
    __shared__ float Ws[512 * 10];
    const int tid = threadIdx.x;
    for (int i = tid; i < 512 * 10; i += 256) Ws[i] = We[i];
    __syncthreads();
    const int lane = tid & 31, w = tid >> 5;
    const int row = blockIdx.x * 8 + w;

    float acc[10];
    #pragma unroll
    for (int c = 0; c < 10; c++) acc[c] = 0.0f;
    for (int k = lane; k < 512; k += 32) {
        float a = __bfloat162float(Ah[row * 512 + k]) +
                  __bfloat162float(Al[row * 512 + k]);
        #pragma unroll
        for (int c = 0; c < 10; c++) acc[c] = fmaf(a, Ws[k * 10 + c], acc[c]);
    }
    #pragma unroll
    for (int c = 0; c < 10; c++) {
        #pragma unroll
        for (int o = 16; o > 0; o >>= 1)
            acc[c] += __shfl_xor_sync(0xffffffffu, acc[c], o);
    }
    if (lane == 0) {
        float v[10], mx = -1e30f;
        #pragma unroll
        for (int c = 0; c < 10; c++) { v[c] = acc[c] + be[c]; mx = fmaxf(mx, v[c]); }
        float s = 0.0f;
        #pragma unroll
        for (int c = 0; c < 10; c++) { v[c] = __expf(v[c] - mx); s += v[c]; }
        float inv = 1.0f / s;
        #pragma unroll
        for (int c = 0; c < 10; c++) out[row * 10 + c] = v[c] * inv;
    }
}

// ---------------------------------------------------------------------------
extern "C" void kernel_launch(void* const* d_in, const int* in_sizes, int n_in,
                              void* d_out, int out_size)
{
    const int*   src = (const int*)  d_in[0];
    const int*   dst = (const int*)  d_in[1];
    const float* W1  = (const float*)d_in[2];
    const float* b1  = (const float*)d_in[3];
    const float* W2  = (const float*)d_in[4];
    const float* b2  = (const float*)d_in[5];
    const float* Wa  = (const float*)d_in[6];
    const float* ba  = (const float*)d_in[7];
    const float* Wb  = (const float*)d_in[8];
    const float* bb  = (const float*)d_in[9];
    const float* Wc  = (const float*)d_in[10];
    const float* bc  = (const float*)d_in[11];
    const float* Wd  = (const float*)d_in[12];
    const float* bd  = (const float*)d_in[13];
    const float* We  = (const float*)d_in[14];
    const float* be  = (const float*)d_in[15];
    float* out = (float*)d_out;

    bf16 *hgh, *hgl, *x1h, *x1l, *x2h, *x2l, *x3h, *x3l, *x4h, *x4l;
    bf16 *wah, *wal, *wbh, *wbl, *wch, *wcl, *wdh, *wdl;
    cudaGetSymbolAddress((void**)&hgh, g_hgh); cudaGetSymbolAddress((void**)&hgl, g_hgl);
    cudaGetSymbolAddress((void**)&x1h, g_x1h); cudaGetSymbolAddress((void**)&x1l, g_x1l);
    cudaGetSymbolAddress((void**)&x2h, g_x2h); cudaGetSymbolAddress((void**)&x2l, g_x2l);
    cudaGetSymbolAddress((void**)&x3h, g_x3h); cudaGetSymbolAddress((void**)&x3l, g_x3l);
    cudaGetSymbolAddress((void**)&x4h, g_x4h); cudaGetSymbolAddress((void**)&x4l, g_x4l);
    cudaGetSymbolAddress((void**)&wah, g_wta_h); cudaGetSymbolAddress((void**)&wal, g_wta_l);
    cudaGetSymbolAddress((void**)&wbh, g_wtb_h); cudaGetSymbolAddress((void**)&wbl, g_wtb_l);
    cudaGetSymbolAddress((void**)&wch, g_wtc_h); cudaGetSymbolAddress((void**)&wcl, g_wtc_l);
    cudaGetSymbolAddress((void**)&wdh, g_wtd_h); cudaGetSymbolAddress((void**)&wdl, g_wtd_l);

    const int SMEM = 224 * CS * 2 + 2 * 208 * TSN * 2 + 4 * 224 * 4 + 256 * 4 + 224;
    cudaFuncSetAttribute(gnn_kernel, cudaFuncAttributeMaxDynamicSharedMemorySize, SMEM);

    conv_w<<<dim3(512 / 32,  128 / 32),  256>>>(Wa, 128,  512,  wah, wal);
    conv_w<<<dim3(1024 / 32, 512 / 32),  256>>>(Wb, 512,  1024, wbh, wbl);
    conv_w<<<dim3(1024 / 32, 1024 / 32), 256>>>(Wc, 1024, 1024, wch, wcl);
    conv_w<<<dim3(512 / 32,  1024 / 32), 256>>>(Wd, 1024, 512,  wdh, wdl);

    precompute_pwl<<<1, 512>>>(W1, b1, W2);
    gnn_kernel<<<NG, 512, SMEM>>>(src, dst, b2, hgh, hgl);

    gemm_bf16<<<dim3(512 / 64,  8), 256>>>(hgh, hgl, wah, wal, ba, x1h, x1l, 128,  512);
    gemm_bf16<<<dim3(1024 / 64, 8), 256>>>(x1h, x1l, wbh, wbl, bb, x2h, x2l, 512,  1024);
    gemm_bf16<<<dim3(1024 / 64, 8), 256>>>(x2h, x2l, wch, wcl, bc, x3h, x3l, 1024, 1024);
    gemm_bf16<<<dim3(512 / 64,  8), 256>>>(x3h, x3l, wdh, wdl, bd, x4h, x4l, 1024, 512);

    head_softmax<<<64, 256>>>(x4h, x4l, We, be, out);
}

// round 8
// speedup vs baseline: 1.4422x; 1.1176x over previous
#include <cuda_runtime.h>
#include <cuda_bf16.h>

#define NG      512
#define NODES   200
#define EDGES   6400
#define HID     128

typedef __nv_bfloat16 bf16;

// ---- activation buffers (bf16 hi/lo pairs) --------------------------------
__device__ bf16 g_hgh[NG * HID],  g_hgl[NG * HID];
__device__ bf16 g_x1h[NG * 512],  g_x1l[NG * 512];
__device__ bf16 g_x2h[NG * 1024], g_x2l[NG * 1024];
__device__ bf16 g_x3h[NG * 1024], g_x3l[NG * 1024];
__device__ bf16 g_x4h[NG * 512],  g_x4l[NG * 512];

// ---- pre-converted transposed weights [N][K] bf16 hi/lo -------------------
__device__ bf16 g_wta_h[512 * 128],   g_wta_l[512 * 128];
__device__ bf16 g_wtb_h[1024 * 512],  g_wtb_l[1024 * 512];
__device__ bf16 g_wtc_h[1024 * 1024], g_wtc_l[1024 * 1024];
__device__ bf16 g_wtd_h[512 * 1024],  g_wtd_l[512 * 1024];

// ---- PWL tables + readiness flag ------------------------------------------
__device__ float g_csorted[128];
__device__ float g_alpha[129 * 128];
__device__ float g_beta[129 * 128];
__device__ unsigned g_pwl_flag = 0;   // reset by head_softmax each launch

// ---- asm helpers -----------------------------------------------------------
__device__ __forceinline__ void cp16(void* smem, const void* gmem) {
    unsigned sa = (unsigned)__cvta_generic_to_shared(smem);
    asm volatile("cp.async.cg.shared.global [%0], [%1], 16;\n" :: "r"(sa), "l"(gmem));
}
__device__ __forceinline__ void cp_commit() {
    asm volatile("cp.async.commit_group;\n");
}
template <int N>
__device__ __forceinline__ void cp_wait() {
    asm volatile("cp.async.wait_group %0;\n" :: "n"(N));
}
__device__ __forceinline__ void ldsm4(unsigned r[4], const void* p) {
    unsigned a = (unsigned)__cvta_generic_to_shared(p);
    asm volatile("ldmatrix.sync.aligned.m8n8.x4.shared.b16 {%0,%1,%2,%3}, [%4];\n"
                 : "=r"(r[0]), "=r"(r[1]), "=r"(r[2]), "=r"(r[3]) : "r"(a));
}
__device__ __forceinline__ void ldsm4t(unsigned r[4], const void* p) {
    unsigned a = (unsigned)__cvta_generic_to_shared(p);
    asm volatile("ldmatrix.sync.aligned.m8n8.x4.trans.shared.b16 {%0,%1,%2,%3}, [%4];\n"
                 : "=r"(r[0]), "=r"(r[1]), "=r"(r[2]), "=r"(r[3]) : "r"(a));
}
__device__ __forceinline__ void mma_bf16(float c[4], const unsigned a[4],
                                         unsigned b0, unsigned b1) {
    asm volatile(
        "mma.sync.aligned.m16n8k16.row.col.f32.bf16.bf16.f32 "
        "{%0,%1,%2,%3}, {%4,%5,%6,%7}, {%8,%9}, {%0,%1,%2,%3};\n"
        : "+f"(c[0]), "+f"(c[1]), "+f"(c[2]), "+f"(c[3])
        : "r"(a[0]), "r"(a[1]), "r"(a[2]), "r"(a[3]), "r"(b0), "r"(b1));
}

// ===========================================================================
// Block type 1: PWL table builder (16 CTAs x 8 segments). tid<128 active.
// ===========================================================================
__device__ void pwl_block(int p, unsigned char* smraw,
    const float* __restrict__ W1, const float* __restrict__ b1,
    const float* __restrict__ W2)
{
    float* sW2 = (float*)smraw;            // 16384 floats (64 KB)
    float* sc  = sW2 + 16384;
    float* sw  = sc + 128;
    float* sb  = sw + 128;
    float* ssc = sb + 128;
    int*  sidx = (int*)(ssc + 128);
    const int tid = threadIdx.x;

    for (int i = tid; i < 4096; i += 512)
        ((float4*)sW2)[i] = ((const float4*)W2)[i];
    if (tid < 128) {
        float w = W1[tid], b = b1[tid];
        sw[tid] = w; sb[tid] = b;
        sc[tid] = (w != 0.0f) ? (-b / w) : __int_as_float(0x7f800000);
    }
    __syncthreads();
    if (tid < 128) {
        float c = sc[tid];
        int r = 0;
        for (int j = 0; j < 128; j++) {
            float cj = sc[j];
            if (cj < c || (cj == c && j < tid)) r++;
        }
        sidx[r] = tid;
        ssc[r]  = c;
    }
    __syncthreads();
    if (tid < 128) {
        if (p == 0) g_csorted[tid] = ssc[tid];
        const int j  = tid;
        const int s0 = p * 8;
        float alpha = 0.0f, beta = 0.0f;
        for (int r = 0; r < 128; r++) {
            int k = sidx[r];
            float w = sw[k], b = sb[k];
            float W2kj = sW2[k * 128 + j];
            if (w == 0.0f) { if (b > 0.0f) beta += b * W2kj; continue; }
            bool active = (w > 0.0f) ? (r < s0) : (r >= s0);
            if (active) { alpha = fmaf(w, W2kj, alpha); beta = fmaf(b, W2kj, beta); }
        }
        for (int s = s0; s < s0 + 8; s++) {
            g_alpha[s * 128 + j] = alpha;
            g_beta[s * 128 + j]  = beta;
            int k = sidx[s];
            float w = sw[k], b = sb[k];
            float W2kj = sW2[k * 128 + j];
            float f = (w > 0.0f) ? 1.0f : ((w < 0.0f) ? -1.0f : 0.0f);
            alpha = fmaf(f * w, W2kj, alpha);
            beta  = fmaf(f * b, W2kj, beta);
        }
        if (p == 15) {
            g_alpha[128 * 128 + j] = alpha;
            g_beta[128 * 128 + j]  = beta;
        }
    }
    __syncthreads();
    if (tid == 0) {
        __threadfence();
        atomicAdd(&g_pwl_flag, 1u);
    }
}

// ===========================================================================
// Block type 2: weight-convert worker (256 CTAs, grid-stride over 2112 tiles)
// W [K][N] fp32 -> Wt_hi/lo [N][K] bf16, 32x32 transpose tiles.
// ===========================================================================
__device__ void conv_block(int w, unsigned char* smraw,
    const float* __restrict__ Wa, const float* __restrict__ Wb,
    const float* __restrict__ Wc, const float* __restrict__ Wd)
{
    float (*tile)[33] = (float(*)[33])smraw;
    const int tid = threadIdx.x;
    const int c = tid & 31, r = tid >> 5;   // r: 0..15

    for (int t = w; t < 2112; t += 256) {
        const float* W; bf16 *Oh, *Ol; int K, N, tl, tn;
        if (t < 64)        { W = Wa; Oh = g_wta_h; Ol = g_wta_l; K = 128;  N = 512;  tl = t;        tn = 16; }
        else if (t < 576)  { W = Wb; Oh = g_wtb_h; Ol = g_wtb_l; K = 512;  N = 1024; tl = t - 64;   tn = 32; }
        else if (t < 1600) { W = Wc; Oh = g_wtc_h; Ol = g_wtc_l; K = 1024; N = 1024; tl = t - 576;  tn = 32; }
        else               { W = Wd; Oh = g_wtd_h; Ol = g_wtd_l; K = 1024; N = 512;  tl = t - 1600; tn = 16; }
        int nb = (tl % tn) * 32, kb = (tl / tn) * 32;
        #pragma unroll
        for (int j = 0; j < 2; j++)
            tile[r + j * 16][c] = W[(size_t)(kb + r + j * 16) * N + nb + c];
        __syncthreads();
        #pragma unroll
        for (int j = 0; j < 2; j++) {
            int n = nb + r + j * 16;
            float v = tile[c][r + j * 16];
            bf16 h = __float2bfloat16(v);
            Oh[(size_t)n * K + kb + c] = h;
            Ol[(size_t)n * K + kb + c] = __float2bfloat16(v - __bfloat162float(h));
        }
        __syncthreads();
    }
}

// ===========================================================================
// Block type 3: per-graph GNN (R7 SpMM version + acquire-wait on PWL tables)
// SMEM = 214,752 B
// ===========================================================================
#define CS 216
#define TSN 136

__device__ void gnn_block(int g, unsigned char* smraw,
    const int* __restrict__ src, const int* __restrict__ dst,
    const float* __restrict__ b2,
    bf16* __restrict__ hgh, bf16* __restrict__ hgl)
{
    bf16*  C    = (bf16*)smraw;
    bf16*  th   = C + 224 * CS;
    bf16*  tl   = th + 208 * TSN;
    float* s_a  = (float*)(tl + 208 * TSN);
    float* s_ii = s_a + 224;
    float* s_io = s_ii + 224;
    float* s_s  = s_io + 224;
    float* pool = s_s + 224;
    unsigned char* seg = (unsigned char*)(pool + 256);

    const int tid   = threadIdx.x;
    const int ebase = g * EDGES;
    const int nbase = g * NODES;

    // --- 1. zero C fully; zero t pad rows ---
    {
        uint4 z = {0, 0, 0, 0};
        uint4* C4 = (uint4*)C;
        for (int i = tid; i < 224 * CS * 2 / 16; i += 512) C4[i] = z;
        uint4* tp = (uint4*)(th + 200 * TSN);
        uint4* lp = (uint4*)(tl + 200 * TSN);
        for (int i = tid; i < 8 * TSN * 2 / 16; i += 512) { tp[i] = z; lp[i] = z; }
    }
    __syncthreads();

    // --- 2. count matrix via bf16x2 atomics ---
    {
        const bf16 one = __float2bfloat16(1.0f);
        const bf16 zer = __float2bfloat16(0.0f);
        __nv_bfloat162 v10 = __halves2bfloat162(one, zer);
        __nv_bfloat162 v01 = __halves2bfloat162(zer, one);
        __nv_bfloat162* C2 = (__nv_bfloat162*)C;
        for (int e = tid; e < EDGES; e += 512) {
            int sl = src[ebase + e] - nbase;
            int dl = dst[ebase + e] - nbase;
            atomicAdd(&C2[dl * (CS / 2) + (sl >> 1)], (sl & 1) ? v01 : v10);
        }
    }
    __syncthreads();

    // --- 3. row sums ---
    if (tid < 224) {
        const __nv_bfloat162* row = (const __nv_bfloat162*)C + tid * (CS / 2);
        float sum = 0.0f;
        for (int w = 0; w < CS / 2; w++) {
            float2 f = __bfloat1622float2(row[w]);
            sum += f.x + f.y;
        }
        s_a[tid]  = sum;
        s_ii[tid] = rsqrtf(fmaxf(sum, 1.0f));
    }
    __syncthreads();

    // --- 4. col sums ---
    if (tid < CS) {
        float sum = 0.0f;
        for (int d = 0; d < NODES; d++) sum += __bfloat162float(C[d * CS + tid]);
        float io = rsqrtf(fmaxf(sum, 1.0f));
        s_io[tid] = io;
        s_s[tid]  = s_a[tid] * io;
    }
    __syncthreads();

    // --- wait for PWL tables (released by 16 pwl CTAs; usually already set) ---
    if (tid == 0) {
        unsigned v;
        do {
            asm volatile("ld.global.acquire.gpu.u32 %0, [%1];"
                         : "=r"(v) : "l"(&g_pwl_flag));
            if (v < 16u) __nanosleep(64);
        } while (v < 16u);
    }
    __syncthreads();

    // --- 5. layer-1 matvec + segment search ---
    if (tid < NODES) {
        const __nv_bfloat162* row = (const __nv_bfloat162*)C + tid * (CS / 2);
        const float2* ss2 = (const float2*)s_s;
        float sum = 0.0f;
        for (int w = 0; w < CS / 2; w++) {
            float2 f = __bfloat1622float2(row[w]);
            float2 s = ss2[w];
            sum = fmaf(f.x, s.x, fmaf(f.y, s.y, sum));
        }
        float a = sum * s_ii[tid];
        s_a[tid] = a;
        int lo = 0, hi = 128;
        while (lo < hi) {
            int m = (lo + hi) >> 1;
            if (g_csorted[m] < a) lo = m + 1; else hi = m;
        }
        seg[tid] = (unsigned char)lo;
    }
    __syncthreads();

    // --- 6. t hi/lo ---
    for (int idx = tid; idx < NODES * 32; idx += 512) {
        int i = idx >> 5, q = idx & 31;
        float a  = s_a[i];
        float io = s_io[i];
        int   s  = seg[i];
        float4 al = ((const float4*)(g_alpha + s * 128))[q];
        float4 be = ((const float4*)(g_beta  + s * 128))[q];
        float v0 = fmaf(al.x, a, be.x) * io;
        float v1 = fmaf(al.y, a, be.y) * io;
        float v2 = fmaf(al.z, a, be.z) * io;
        float v3 = fmaf(al.w, a, be.w) * io;
        bf16 h0 = __float2bfloat16(v0), h1 = __float2bfloat16(v1);
        bf16 h2 = __float2bfloat16(v2), h3 = __float2bfloat16(v3);
        __nv_bfloat162 hp0 = __halves2bfloat162(h0, h1);
        __nv_bfloat162 hp1 = __halves2bfloat162(h2, h3);
        __nv_bfloat162 lp0 = __halves2bfloat162(
            __float2bfloat16(v0 - __bfloat162float(h0)),
            __float2bfloat16(v1 - __bfloat162float(h1)));
        __nv_bfloat162 lp1 = __halves2bfloat162(
            __float2bfloat16(v2 - __bfloat162float(h2)),
            __float2bfloat16(v3 - __bfloat162float(h3)));
        __nv_bfloat162* dh = (__nv_bfloat162*)(th + i * TSN + q * 4);
        __nv_bfloat162* dl = (__nv_bfloat162*)(tl + i * TSN + q * 4);
        dh[0] = hp0; dh[1] = hp1;
        dl[0] = lp0; dl[1] = lp1;
    }
    __syncthreads();

    // --- 7. MMA: acc = C @ (th + tl) ---
    const int lane = tid & 31;
    const int wid  = tid >> 5;
    const int wm   = wid & 1;
    const int wn   = wid >> 1;

    float c[7][2][4];
    #pragma unroll
    for (int mi = 0; mi < 7; mi++)
        #pragma unroll
        for (int ni = 0; ni < 2; ni++)
            #pragma unroll
            for (int q = 0; q < 4; q++) c[mi][ni][q] = 0.0f;

    const int aRow = wm * 112 + (lane & 15);
    const int aCol = ((lane >> 4) & 1) * 8;
    const int bRow = (lane & 7) + ((lane >> 4) & 1) * 8;
    const int bCol = wn * 16 + ((lane >> 3) & 1) * 8;

    for (int kt = 0; kt < 13; kt++) {
        unsigned bh[4], bl[4];
        const int kr = kt * 16 + bRow;
        ldsm4t(bh, th + kr * TSN + bCol);
        ldsm4t(bl, tl + kr * TSN + bCol);
        #pragma unroll
        for (int mi = 0; mi < 7; mi++) {
            unsigned af[4];
            ldsm4(af, C + (aRow + mi * 16) * CS + kt * 16 + aCol);
            mma_bf16(c[mi][0], af, bh[0], bh[2]);
            mma_bf16(c[mi][0], af, bl[0], bl[2]);
            mma_bf16(c[mi][1], af, bh[1], bh[3]);
            mma_bf16(c[mi][1], af, bl[1], bl[3]);
        }
    }

    // --- 8. epilogue: relu + fused pool ---
    {
        const int gg = lane >> 2;
        const int tg = lane & 3;
        float bx[2], by[2];
        #pragma unroll
        for (int ni = 0; ni < 2; ni++) {
            int col = wn * 16 + ni * 8 + tg * 2;
            float2 bv = *(const float2*)(b2 + col);
            bx[ni] = bv.x; by[ni] = bv.y;
        }
        float ps[2][2] = {{0, 0}, {0, 0}};
        #pragma unroll
        for (int mi = 0; mi < 7; mi++) {
            int r0 = wm * 112 + mi * 16 + gg;
            int r1 = r0 + 8;
            float ii0 = (r0 < NODES) ? s_ii[r0] : 0.0f;
            float ii1 = (r1 < NODES) ? s_ii[r1] : 0.0f;
            #pragma unroll
            for (int ni = 0; ni < 2; ni++) {
                if (r0 < NODES) {
                    ps[ni][0] += fmaxf(fmaf(c[mi][ni][0], ii0, bx[ni]), 0.0f);
                    ps[ni][1] += fmaxf(fmaf(c[mi][ni][1], ii0, by[ni]), 0.0f);
                }
                if (r1 < NODES) {
                    ps[ni][0] += fmaxf(fmaf(c[mi][ni][2], ii1, bx[ni]), 0.0f);
                    ps[ni][1] += fmaxf(fmaf(c[mi][ni][3], ii1, by[ni]), 0.0f);
                }
            }
        }
        #pragma unroll
        for (int off = 16; off >= 4; off >>= 1) {
            #pragma unroll
            for (int ni = 0; ni < 2; ni++) {
                ps[ni][0] += __shfl_down_sync(0xffffffffu, ps[ni][0], off);
                ps[ni][1] += __shfl_down_sync(0xffffffffu, ps[ni][1], off);
            }
        }
        if (lane < 4) {
            #pragma unroll
            for (int ni = 0; ni < 2; ni++) {
                int col = wn * 16 + ni * 8 + lane * 2;
                pool[wm * 128 + col]     = ps[ni][0];
                pool[wm * 128 + col + 1] = ps[ni][1];
            }
        }
    }
    __syncthreads();
    if (tid < HID) {
        float v = (pool[tid] + pool[128 + tid]) * (1.0f / 200.0f);
        bf16 h = __float2bfloat16(v);
        hgh[g * HID + tid] = h;
        hgl[g * HID + tid] = __float2bfloat16(v - __bfloat162float(h));
    }
}

// ===========================================================================
// Merged prep + GNN kernel. Grid = 784 CTAs x 512 threads.
//   bid 0..15    : pwl
//   bid 16..147  : gnn graphs 0..131     (wave 1 = pwl + gnn)
//   bid 148..403 : conv workers 0..255
//   bid 404..783 : gnn graphs 132..511
// ===========================================================================
__global__ void __launch_bounds__(512, 1) prep_gnn(
    const int* __restrict__ src, const int* __restrict__ dst,
    const float* __restrict__ W1, const float* __restrict__ b1,
    const float* __restrict__ W2, const float* __restrict__ b2,
    const float* __restrict__ Wa, const float* __restrict__ Wb,
    const float* __restrict__ Wc, const float* __restrict__ Wd,
    bf16* __restrict__ hgh, bf16* __restrict__ hgl)
{
    extern __shared__ unsigned char smraw[];
    const int bid = blockIdx.x;
    if (bid < 16)       pwl_block(bid, smraw, W1, b1, W2);
    else if (bid < 148) gnn_block(bid - 16, smraw, src, dst, b2, hgh, hgl);
    else if (bid < 404) conv_block(bid - 148, smraw, Wa, Wb, Wc, Wd);
    else                gnn_block(bid - 404 + 132, smraw, src, dst, b2, hgh, hgl);
}

// ---------------------------------------------------------------------------
// bf16 hi/lo tensor-core GEMM (unchanged from R6/R7, working).
// ---------------------------------------------------------------------------
#define TSB 40

__global__ void __launch_bounds__(256) gemm_bf16(
    const bf16* __restrict__ Ah, const bf16* __restrict__ Al,
    const bf16* __restrict__ Bh, const bf16* __restrict__ Bl,
    const float* __restrict__ bias,
    bf16* __restrict__ Oh, bf16* __restrict__ Ol,
    int K, int Nc)
{
    __shared__ bf16 sAh[2][64 * TSB], sAl[2][64 * TSB];
    __shared__ bf16 sBh[2][64 * TSB], sBl[2][64 * TSB];

    const int tid  = threadIdx.x;
    const int lane = tid & 31;
    const int wid  = tid >> 5;
    const int wm   = wid & 1;
    const int wn   = wid >> 1;
    const int row0 = blockIdx.y * 64, col0 = blockIdx.x * 64;

    const int th  = tid & 127;
    const int lr  = th >> 2;
    const int lc  = (th & 3) * 8;
    const bool pl = (tid < 128);

    const bf16* gA = (pl ? Ah : Al) + (size_t)(row0 + lr) * K + lc;
    const bf16* gB = (pl ? Bh : Bl) + (size_t)(col0 + lr) * K + lc;
    bf16* dA0 = (pl ? sAh[0] : sAl[0]) + lr * TSB + lc;
    bf16* dB0 = (pl ? sBh[0] : sBl[0]) + lr * TSB + lc;
    bf16* dA1 = (pl ? sAh[1] : sAl[1]) + lr * TSB + lc;
    bf16* dB1 = (pl ? sBh[1] : sBl[1]) + lr * TSB + lc;

    float c[2][2][4];
    #pragma unroll
    for (int mi = 0; mi < 2; mi++)
        #pragma unroll
        for (int ni = 0; ni < 2; ni++)
            #pragma unroll
            for (int q = 0; q < 4; q++) c[mi][ni][q] = 0.0f;

    cp16(dA0, gA);                cp16(dA0 + 32 * TSB, gA + (size_t)32 * K);
    cp16(dB0, gB);                cp16(dB0 + 32 * TSB, gB + (size_t)32 * K);
    cp_commit();

    const int nkt = K >> 5;
    const int frow = lane & 15;
    const int fk   = (lane >> 4) * 8;
    int buf = 0;

    for (int kt = 0; kt < nkt; kt++) {
        if (kt + 1 < nkt) {
            const bf16* gA1 = gA + (size_t)(kt + 1) * 32;
            const bf16* gB1 = gB + (size_t)(kt + 1) * 32;
            bf16* dA = buf ? dA0 : dA1;
            bf16* dB = buf ? dB0 : dB1;
            cp16(dA, gA1); cp16(dA + 32 * TSB, gA1 + (size_t)32 * K);
            cp16(dB, gB1); cp16(dB + 32 * TSB, gB1 + (size_t)32 * K);
            cp_commit();
            cp_wait<1>();
        } else {
            cp_wait<0>();
        }
        __syncthreads();

        #pragma unroll
        for (int ks = 0; ks < 32; ks += 16) {
            unsigned ah[2][4], al[2][4], bh[4], bl[4];
            #pragma unroll
            for (int mi = 0; mi < 2; mi++) {
                int ro = (wm * 32 + mi * 16 + frow) * TSB + ks + fk;
                ldsm4(ah[mi], &sAh[buf][ro]);
                ldsm4(al[mi], &sAl[buf][ro]);
            }
            {
                int no = (wn * 16 + frow) * TSB + ks + fk;
                ldsm4(bh, &sBh[buf][no]);
                ldsm4(bl, &sBl[buf][no]);
            }
            #pragma unroll
            for (int mi = 0; mi < 2; mi++)
                #pragma unroll
                for (int ni = 0; ni < 2; ni++) {
                    unsigned b0h = ni ? bh[1] : bh[0], b1h = ni ? bh[3] : bh[2];
                    unsigned b0l = ni ? bl[1] : bl[0], b1l = ni ? bl[3] : bl[2];
                    mma_bf16(c[mi][ni], ah[mi], b0h, b1h);
                    mma_bf16(c[mi][ni], ah[mi], b0l, b1l);
                    mma_bf16(c[mi][ni], al[mi], b0h, b1h);
                }
        }
        __syncthreads();
        buf ^= 1;
    }

    const int g  = lane >> 2;
    const int tg = lane & 3;
    #pragma unroll
    for (int mi = 0; mi < 2; mi++) {
        #pragma unroll
        for (int ni = 0; ni < 2; ni++) {
            int r  = row0 + wm * 32 + mi * 16 + g;
            int cc = col0 + wn * 16 + ni * 8 + tg * 2;
            float2 bv = *(const float2*)(bias + cc);
            #pragma unroll
            for (int half = 0; half < 2; half++) {
                int rr = r + half * 8;
                float vx = fmaxf(c[mi][ni][half * 2 + 0] + bv.x, 0.0f);
                float vy = fmaxf(c[mi][ni][half * 2 + 1] + bv.y, 0.0f);
                bf16 hx = __float2bfloat16(vx);
                bf16 hy = __float2bfloat16(vy);
                __nv_bfloat162 hp(hx, hy);
                __nv_bfloat162 lp(__float2bfloat16(vx - __bfloat162float(hx)),
                                  __float2bfloat16(vy - __bfloat162float(hy)));
                *(__nv_bfloat162*)(Oh + (size_t)rr * Nc + cc) = hp;
                *(__nv_bfloat162*)(Ol + (size_t)rr * Nc + cc) = lp;
            }
        }
    }
}

// ---------------------------------------------------------------------------
// Final layer + flag reset for the next replay.
// ---------------------------------------------------------------------------
__global__ void __launch_bounds__(256) head_softmax(
    const bf16* __restrict__ Ah, const bf16* __restrict__ Al,
    const float* __restrict__ We, const float* __restrict__ be,
    float* __restrict__ out)
{
    if (blockIdx.x == 0 && threadIdx.x == 0) g_pwl_flag = 0;

    __shared__ float Ws[512 * 10];
    const int tid = threadIdx.x;
    for (int i = tid; i < 512 * 10; i += 256) Ws[i] = We[i];
    __syncthreads();
    const int lane = tid & 31, w = tid >> 5;
    const int row = blockIdx.x * 8 + w;

    float acc[10];
    #pragma unroll
    for (int c = 0; c < 10; c++) acc[c] = 0.0f;
    for (int k = lane; k < 512; k += 32) {
        float a = __bfloat162float(Ah[row * 512 + k]) +
                  __bfloat162float(Al[row * 512 + k]);
        #pragma unroll
        for (int c = 0; c < 10; c++) acc[c] = fmaf(a, Ws[k * 10 + c], acc[c]);
    }
    #pragma unroll
    for (int c = 0; c < 10; c++) {
        #pragma unroll
        for (int o = 16; o > 0; o >>= 1)
            acc[c] += __shfl_xor_sync(0xffffffffu, acc[c], o);
    }
    if (lane == 0) {
        float v[10], mx = -1e30f;
        #pragma unroll
        for (int c = 0; c < 10; c++) { v[c] = acc[c] + be[c]; mx = fmaxf(mx, v[c]); }
        float s = 0.0f;
        #pragma unroll
        for (int c = 0; c < 10; c++) { v[c] = __expf(v[c] - mx); s += v[c]; }
        float inv = 1.0f / s;
        #pragma unroll
        for (int c = 0; c < 10; c++) out[row * 10 + c] = v[c] * inv;
    }
}

// ---------------------------------------------------------------------------
extern "C" void kernel_launch(void* const* d_in, const int* in_sizes, int n_in,
                              void* d_out, int out_size)
{
    const int*   src = (const int*)  d_in[0];
    const int*   dst = (const int*)  d_in[1];
    const float* W1  = (const float*)d_in[2];
    const float* b1  = (const float*)d_in[3];
    const float* W2  = (const float*)d_in[4];
    const float* b2  = (const float*)d_in[5];
    const float* Wa  = (const float*)d_in[6];
    const float* ba  = (const float*)d_in[7];
    const float* Wb  = (const float*)d_in[8];
    const float* bb  = (const float*)d_in[9];
    const float* Wc  = (const float*)d_in[10];
    const float* bc  = (const float*)d_in[11];
    const float* Wd  = (const float*)d_in[12];
    const float* bd  = (const float*)d_in[13];
    const float* We  = (const float*)d_in[14];
    const float* be  = (const float*)d_in[15];
    float* out = (float*)d_out;

    bf16 *hgh, *hgl, *x1h, *x1l, *x2h, *x2l, *x3h, *x3l, *x4h, *x4l;
    bf16 *wah, *wal, *wbh, *wbl, *wch, *wcl, *wdh, *wdl;
    cudaGetSymbolAddress((void**)&hgh, g_hgh); cudaGetSymbolAddress((void**)&hgl, g_hgl);
    cudaGetSymbolAddress((void**)&x1h, g_x1h); cudaGetSymbolAddress((void**)&x1l, g_x1l);
    cudaGetSymbolAddress((void**)&x2h, g_x2h); cudaGetSymbolAddress((void**)&x2l, g_x2l);
    cudaGetSymbolAddress((void**)&x3h, g_x3h); cudaGetSymbolAddress((void**)&x3l, g_x3l);
    cudaGetSymbolAddress((void**)&x4h, g_x4h); cudaGetSymbolAddress((void**)&x4l, g_x4l);
    cudaGetSymbolAddress((void**)&wah, g_wta_h); cudaGetSymbolAddress((void**)&wal, g_wta_l);
    cudaGetSymbolAddress((void**)&wbh, g_wtb_h); cudaGetSymbolAddress((void**)&wbl, g_wtb_l);
    cudaGetSymbolAddress((void**)&wch, g_wtc_h); cudaGetSymbolAddress((void**)&wcl, g_wtc_l);
    cudaGetSymbolAddress((void**)&wdh, g_wtd_h); cudaGetSymbolAddress((void**)&wdl, g_wtd_l);

    const int SMEM = 224 * CS * 2 + 2 * 208 * TSN * 2 + 4 * 224 * 4 + 256 * 4 + 224;
    cudaFuncSetAttribute(prep_gnn, cudaFuncAttributeMaxDynamicSharedMemorySize, SMEM);

    prep_gnn<<<784, 512, SMEM>>>(src, dst, W1, b1, W2, b2, Wa, Wb, Wc, Wd, hgh, hgl);

    gemm_bf16<<<dim3(512 / 64,  8), 256>>>(hgh, hgl, wah, wal, ba, x1h, x1l, 128,  512);
    gemm_bf16<<<dim3(1024 / 64, 8), 256>>>(x1h, x1l, wbh, wbl, bb, x2h, x2l, 512,  1024);
    gemm_bf16<<<dim3(1024 / 64, 8), 256>>>(x2h, x2l, wch, wcl, bc, x3h, x3l, 1024, 1024);
    gemm_bf16<<<dim3(512 / 64,  8), 256>>>(x3h, x3l, wdh, wdl, bd, x4h, x4l, 1024, 512);

    head_softmax<<<64, 256>>>(x4h, x4l, We, be, out);
}

// round 9
// speedup vs baseline: 1.5071x; 1.0450x over previous
#include <cuda_runtime.h>
#include <cuda_bf16.h>

#define NG      512
#define NODES   200
#define EDGES   6400
#define HID     128

typedef __nv_bfloat16 bf16;

// ---- activation buffers (bf16 hi/lo pairs) --------------------------------
__device__ bf16 g_hgh[NG * HID],  g_hgl[NG * HID];
__device__ bf16 g_x1h[NG * 512],  g_x1l[NG * 512];
__device__ bf16 g_x2h[NG * 1024], g_x2l[NG * 1024];
__device__ bf16 g_x3h[NG * 1024], g_x3l[NG * 1024];
__device__ bf16 g_x4h[NG * 512],  g_x4l[NG * 512];

// ---- pre-converted transposed weights [N][K] bf16 hi/lo -------------------
__device__ bf16 g_wta_h[512 * 128],   g_wta_l[512 * 128];
__device__ bf16 g_wtb_h[1024 * 512],  g_wtb_l[1024 * 512];
__device__ bf16 g_wtc_h[1024 * 1024], g_wtc_l[1024 * 1024];
__device__ bf16 g_wtd_h[512 * 1024],  g_wtd_l[512 * 1024];

// ---- PWL tables + readiness flag ------------------------------------------
__device__ float g_csorted[128];
__device__ float g_alpha[129 * 128];
__device__ float g_beta[129 * 128];
__device__ unsigned g_pwl_flag = 0;   // reset by head_softmax each launch

// ---- asm helpers -----------------------------------------------------------
__device__ __forceinline__ void cp16(void* smem, const void* gmem) {
    unsigned sa = (unsigned)__cvta_generic_to_shared(smem);
    asm volatile("cp.async.cg.shared.global [%0], [%1], 16;\n" :: "r"(sa), "l"(gmem));
}
__device__ __forceinline__ void cp_commit() {
    asm volatile("cp.async.commit_group;\n");
}
template <int N>
__device__ __forceinline__ void cp_wait() {
    asm volatile("cp.async.wait_group %0;\n" :: "n"(N));
}
__device__ __forceinline__ void ldsm4(unsigned r[4], const void* p) {
    unsigned a = (unsigned)__cvta_generic_to_shared(p);
    asm volatile("ldmatrix.sync.aligned.m8n8.x4.shared.b16 {%0,%1,%2,%3}, [%4];\n"
                 : "=r"(r[0]), "=r"(r[1]), "=r"(r[2]), "=r"(r[3]) : "r"(a));
}
__device__ __forceinline__ void ldsm4t(unsigned r[4], const void* p) {
    unsigned a = (unsigned)__cvta_generic_to_shared(p);
    asm volatile("ldmatrix.sync.aligned.m8n8.x4.trans.shared.b16 {%0,%1,%2,%3}, [%4];\n"
                 : "=r"(r[0]), "=r"(r[1]), "=r"(r[2]), "=r"(r[3]) : "r"(a));
}
__device__ __forceinline__ void mma_bf16(float c[4], const unsigned a[4],
                                         unsigned b0, unsigned b1) {
    asm volatile(
        "mma.sync.aligned.m16n8k16.row.col.f32.bf16.bf16.f32 "
        "{%0,%1,%2,%3}, {%4,%5,%6,%7}, {%8,%9}, {%0,%1,%2,%3};\n"
        : "+f"(c[0]), "+f"(c[1]), "+f"(c[2]), "+f"(c[3])
        : "r"(a[0]), "r"(a[1]), "r"(a[2]), "r"(a[3]), "r"(b0), "r"(b1));
}

// ===========================================================================
// PWL table builder (bids 0..15, 8 segments each). tid<128 active.
// ===========================================================================
__device__ void pwl_block(int p, unsigned char* smraw,
    const float* __restrict__ W1, const float* __restrict__ b1,
    const float* __restrict__ W2)
{
    float* sW2 = (float*)smraw;            // 16384 floats
    float* sc  = sW2 + 16384;
    float* sw  = sc + 128;
    float* sb  = sw + 128;
    float* ssc = sb + 128;
    int*  sidx = (int*)(ssc + 128);
    const int tid = threadIdx.x;

    for (int i = tid; i < 4096; i += 512)
        ((float4*)sW2)[i] = ((const float4*)W2)[i];
    if (tid < 128) {
        float w = W1[tid], b = b1[tid];
        sw[tid] = w; sb[tid] = b;
        sc[tid] = (w != 0.0f) ? (-b / w) : __int_as_float(0x7f800000);
    }
    __syncthreads();
    if (tid < 128) {
        float c = sc[tid];
        int r = 0;
        for (int j = 0; j < 128; j++) {
            float cj = sc[j];
            if (cj < c || (cj == c && j < tid)) r++;
        }
        sidx[r] = tid;
        ssc[r]  = c;
    }
    __syncthreads();
    if (tid < 128) {
        if (p == 0) g_csorted[tid] = ssc[tid];
        const int j  = tid;
        const int s0 = p * 8;
        float alpha = 0.0f, beta = 0.0f;
        for (int r = 0; r < 128; r++) {
            int k = sidx[r];
            float w = sw[k], b = sb[k];
            float W2kj = sW2[k * 128 + j];
            if (w == 0.0f) { if (b > 0.0f) beta += b * W2kj; continue; }
            bool active = (w > 0.0f) ? (r < s0) : (r >= s0);
            if (active) { alpha = fmaf(w, W2kj, alpha); beta = fmaf(b, W2kj, beta); }
        }
        for (int s = s0; s < s0 + 8; s++) {
            g_alpha[s * 128 + j] = alpha;
            g_beta[s * 128 + j]  = beta;
            int k = sidx[s];
            float w = sw[k], b = sb[k];
            float W2kj = sW2[k * 128 + j];
            float f = (w > 0.0f) ? 1.0f : ((w < 0.0f) ? -1.0f : 0.0f);
            alpha = fmaf(f * w, W2kj, alpha);
            beta  = fmaf(f * b, W2kj, beta);
        }
        if (p == 15) {
            g_alpha[128 * 128 + j] = alpha;
            g_beta[128 * 128 + j]  = beta;
        }
    }
    __syncthreads();
    if (tid == 0) {
        __threadfence();
        atomicAdd(&g_pwl_flag, 1u);
    }
}

// ===========================================================================
// Weight-convert prologue: grid-stride over 2112 32x32 transpose tiles.
// ===========================================================================
__device__ void conv_block(int w, int stride, unsigned char* smraw,
    const float* __restrict__ Wa, const float* __restrict__ Wb,
    const float* __restrict__ Wc, const float* __restrict__ Wd)
{
    float (*tile)[33] = (float(*)[33])smraw;
    const int tid = threadIdx.x;
    const int c = tid & 31, r = tid >> 5;   // r: 0..15

    for (int t = w; t < 2112; t += stride) {
        const float* W; bf16 *Oh, *Ol; int K, N, tl, tn;
        if (t < 64)        { W = Wa; Oh = g_wta_h; Ol = g_wta_l; K = 128;  N = 512;  tl = t;        tn = 16; }
        else if (t < 576)  { W = Wb; Oh = g_wtb_h; Ol = g_wtb_l; K = 512;  N = 1024; tl = t - 64;   tn = 32; }
        else if (t < 1600) { W = Wc; Oh = g_wtc_h; Ol = g_wtc_l; K = 1024; N = 1024; tl = t - 576;  tn = 32; }
        else               { W = Wd; Oh = g_wtd_h; Ol = g_wtd_l; K = 1024; N = 512;  tl = t - 1600; tn = 16; }
        int nb = (tl % tn) * 32, kb = (tl / tn) * 32;
        #pragma unroll
        for (int j = 0; j < 2; j++)
            tile[r + j * 16][c] = W[(size_t)(kb + r + j * 16) * N + nb + c];
        __syncthreads();
        #pragma unroll
        for (int j = 0; j < 2; j++) {
            int n = nb + r + j * 16;
            float v = tile[c][r + j * 16];
            bf16 h = __float2bfloat16(v);
            Oh[(size_t)n * K + kb + c] = h;
            Ol[(size_t)n * K + kb + c] = __float2bfloat16(v - __bfloat162float(h));
        }
        __syncthreads();
    }
}

// ===========================================================================
// Per-graph GNN block (SpMM via legacy mma; reordered MMA rounds).
// SMEM = 216,544 B
// ===========================================================================
#define CS 216
#define TSN 136

__device__ void gnn_block(int g, unsigned char* smraw,
    const int* __restrict__ src, const int* __restrict__ dst,
    const float* __restrict__ b2,
    bf16* __restrict__ hgh, bf16* __restrict__ hgl)
{
    bf16*  C    = (bf16*)smraw;
    bf16*  th   = C + 224 * CS;
    bf16*  tl   = th + 208 * TSN;
    float* s_a  = (float*)(tl + 208 * TSN);
    float* s_ii = s_a + 224;
    float* s_io = s_ii + 224;
    float* s_s  = s_io + 224;
    float* pool = s_s + 224;                 // 256
    float* colp = pool + 256;                // 448
    unsigned char* seg = (unsigned char*)(colp + 448); // 224

    const int tid   = threadIdx.x;
    const int ebase = g * EDGES;
    const int nbase = g * NODES;

    __syncthreads();   // smem handoff from pwl/conv prologue

    // --- 1. zero C fully; zero t pad rows ---
    {
        uint4 z = {0, 0, 0, 0};
        uint4* C4 = (uint4*)C;
        for (int i = tid; i < 224 * CS * 2 / 16; i += 512) C4[i] = z;
        uint4* tp = (uint4*)(th + 200 * TSN);
        uint4* lp = (uint4*)(tl + 200 * TSN);
        for (int i = tid; i < 8 * TSN * 2 / 16; i += 512) { tp[i] = z; lp[i] = z; }
    }
    __syncthreads();

    // --- 2. count matrix via bf16x2 atomics ---
    {
        const bf16 one = __float2bfloat16(1.0f);
        const bf16 zer = __float2bfloat16(0.0f);
        __nv_bfloat162 v10 = __halves2bfloat162(one, zer);
        __nv_bfloat162 v01 = __halves2bfloat162(zer, one);
        __nv_bfloat162* C2 = (__nv_bfloat162*)C;
        for (int e = tid; e < EDGES; e += 512) {
            int sl = src[ebase + e] - nbase;
            int dl = dst[ebase + e] - nbase;
            atomicAdd(&C2[dl * (CS / 2) + (sl >> 1)], (sl & 1) ? v01 : v10);
        }
    }
    __syncthreads();

    // --- 3. row sums (2-way split) ---
    if (tid < 448) {
        int r = tid % 224, half = tid / 224;
        const __nv_bfloat162* row = (const __nv_bfloat162*)C + r * (CS / 2) + half * 54;
        float sum = 0.0f;
        for (int w = 0; w < 54; w++) {
            float2 f = __bfloat1622float2(row[w]);
            sum += f.x + f.y;
        }
        colp[tid] = sum;
    }
    __syncthreads();
    if (tid < 224) {
        float sum = colp[tid] + colp[224 + tid];
        s_a[tid]  = sum;
        s_ii[tid] = rsqrtf(fmaxf(sum, 1.0f));
    }
    __syncthreads();

    // --- 4. col sums (2-way split over rows) ---
    if (tid < 432) {
        int cc = tid % 216, half = tid / 216;
        float sum = 0.0f;
        for (int d = half * 100; d < half * 100 + 100; d++)
            sum += __bfloat162float(C[d * CS + cc]);
        colp[tid] = sum;
    }
    __syncthreads();
    if (tid < CS) {
        float sum = colp[tid] + colp[216 + tid];
        float io = rsqrtf(fmaxf(sum, 1.0f));
        s_io[tid] = io;
        s_s[tid]  = s_a[tid] * io;
    }
    __syncthreads();

    // --- wait for PWL tables ---
    if (tid == 0) {
        unsigned v;
        do {
            asm volatile("ld.global.acquire.gpu.u32 %0, [%1];"
                         : "=r"(v) : "l"(&g_pwl_flag));
            if (v < 16u) __nanosleep(64);
        } while (v < 16u);
    }
    __syncthreads();

    // --- 5. layer-1 matvec (2-way split) + segment search ---
    if (tid < 400) {
        int d = tid % 200, half = tid / 200;
        const __nv_bfloat162* row = (const __nv_bfloat162*)C + d * (CS / 2) + half * 54;
        const float2* ss2 = (const float2*)s_s + half * 54;
        float sum = 0.0f;
        for (int w = 0; w < 54; w++) {
            float2 f = __bfloat1622float2(row[w]);
            float2 s = ss2[w];
            sum = fmaf(f.x, s.x, fmaf(f.y, s.y, sum));
        }
        colp[tid] = sum;
    }
    __syncthreads();
    if (tid < NODES) {
        float a = (colp[tid] + colp[200 + tid]) * s_ii[tid];
        s_a[tid] = a;
        int lo = 0, hi = 128;
        while (lo < hi) {
            int m = (lo + hi) >> 1;
            if (g_csorted[m] < a) lo = m + 1; else hi = m;
        }
        seg[tid] = (unsigned char)lo;
    }
    __syncthreads();

    // --- 6. t hi/lo ---
    for (int idx = tid; idx < NODES * 32; idx += 512) {
        int i = idx >> 5, q = idx & 31;
        float a  = s_a[i];
        float io = s_io[i];
        int   s  = seg[i];
        float4 al = ((const float4*)(g_alpha + s * 128))[q];
        float4 be = ((const float4*)(g_beta  + s * 128))[q];
        float v0 = fmaf(al.x, a, be.x) * io;
        float v1 = fmaf(al.y, a, be.y) * io;
        float v2 = fmaf(al.z, a, be.z) * io;
        float v3 = fmaf(al.w, a, be.w) * io;
        bf16 h0 = __float2bfloat16(v0), h1 = __float2bfloat16(v1);
        bf16 h2 = __float2bfloat16(v2), h3 = __float2bfloat16(v3);
        __nv_bfloat162 hp0 = __halves2bfloat162(h0, h1);
        __nv_bfloat162 hp1 = __halves2bfloat162(h2, h3);
        __nv_bfloat162 lp0 = __halves2bfloat162(
            __float2bfloat16(v0 - __bfloat162float(h0)),
            __float2bfloat16(v1 - __bfloat162float(h1)));
        __nv_bfloat162 lp1 = __halves2bfloat162(
            __float2bfloat16(v2 - __bfloat162float(h2)),
            __float2bfloat16(v3 - __bfloat162float(h3)));
        __nv_bfloat162* dh = (__nv_bfloat162*)(th + i * TSN + q * 4);
        __nv_bfloat162* dl = (__nv_bfloat162*)(tl + i * TSN + q * 4);
        dh[0] = hp0; dh[1] = hp1;
        dl[0] = lp0; dl[1] = lp1;
    }
    __syncthreads();

    // --- 7. MMA: acc = C @ (th + tl), rounds reordered for ILP ---
    const int lane = tid & 31;
    const int wid  = tid >> 5;
    const int wm   = wid & 1;
    const int wn   = wid >> 1;

    float c[7][2][4];
    #pragma unroll
    for (int mi = 0; mi < 7; mi++)
        #pragma unroll
        for (int ni = 0; ni < 2; ni++)
            #pragma unroll
            for (int q = 0; q < 4; q++) c[mi][ni][q] = 0.0f;

    const int aRow = wm * 112 + (lane & 15);
    const int aCol = ((lane >> 4) & 1) * 8;
    const int bRow = (lane & 7) + ((lane >> 4) & 1) * 8;
    const int bCol = wn * 16 + ((lane >> 3) & 1) * 8;

    for (int kt = 0; kt < 13; kt++) {
        unsigned bh[4], bl[4], af[7][4];
        const int kr = kt * 16 + bRow;
        ldsm4t(bh, th + kr * TSN + bCol);
        ldsm4t(bl, tl + kr * TSN + bCol);
        #pragma unroll
        for (int mi = 0; mi < 7; mi++)
            ldsm4(af[mi], C + (aRow + mi * 16) * CS + kt * 16 + aCol);
        #pragma unroll
        for (int mi = 0; mi < 7; mi++) mma_bf16(c[mi][0], af[mi], bh[0], bh[2]);
        #pragma unroll
        for (int mi = 0; mi < 7; mi++) mma_bf16(c[mi][1], af[mi], bh[1], bh[3]);
        #pragma unroll
        for (int mi = 0; mi < 7; mi++) mma_bf16(c[mi][0], af[mi], bl[0], bl[2]);
        #pragma unroll
        for (int mi = 0; mi < 7; mi++) mma_bf16(c[mi][1], af[mi], bl[1], bl[3]);
    }

    // --- 8. epilogue: relu + fused pool ---
    {
        const int gg = lane >> 2;
        const int tg = lane & 3;
        float bx[2], by[2];
        #pragma unroll
        for (int ni = 0; ni < 2; ni++) {
            int col = wn * 16 + ni * 8 + tg * 2;
            float2 bv = *(const float2*)(b2 + col);
            bx[ni] = bv.x; by[ni] = bv.y;
        }
        float ps[2][2] = {{0, 0}, {0, 0}};
        #pragma unroll
        for (int mi = 0; mi < 7; mi++) {
            int r0 = wm * 112 + mi * 16 + gg;
            int r1 = r0 + 8;
            float ii0 = (r0 < NODES) ? s_ii[r0] : 0.0f;
            float ii1 = (r1 < NODES) ? s_ii[r1] : 0.0f;
            #pragma unroll
            for (int ni = 0; ni < 2; ni++) {
                if (r0 < NODES) {
                    ps[ni][0] += fmaxf(fmaf(c[mi][ni][0], ii0, bx[ni]), 0.0f);
                    ps[ni][1] += fmaxf(fmaf(c[mi][ni][1], ii0, by[ni]), 0.0f);
                }
                if (r1 < NODES) {
                    ps[ni][0] += fmaxf(fmaf(c[mi][ni][2], ii1, bx[ni]), 0.0f);
                    ps[ni][1] += fmaxf(fmaf(c[mi][ni][3], ii1, by[ni]), 0.0f);
                }
            }
        }
        #pragma unroll
        for (int off = 16; off >= 4; off >>= 1) {
            #pragma unroll
            for (int ni = 0; ni < 2; ni++) {
                ps[ni][0] += __shfl_down_sync(0xffffffffu, ps[ni][0], off);
                ps[ni][1] += __shfl_down_sync(0xffffffffu, ps[ni][1], off);
            }
        }
        if (lane < 4) {
            #pragma unroll
            for (int ni = 0; ni < 2; ni++) {
                int col = wn * 16 + ni * 8 + lane * 2;
                pool[wm * 128 + col]     = ps[ni][0];
                pool[wm * 128 + col + 1] = ps[ni][1];
            }
        }
    }
    __syncthreads();
    if (tid < HID) {
        float v = (pool[tid] + pool[128 + tid]) * (1.0f / 200.0f);
        bf16 h = __float2bfloat16(v);
        hgh[g * HID + tid] = h;
        hgl[g * HID + tid] = __float2bfloat16(v - __bfloat162float(h));
    }
}

// ===========================================================================
// Merged kernel: 512 CTAs x 512 threads. bid<16: pwl; bid>=16: conv prologue;
// all: gnn for graph bid.
// ===========================================================================
__global__ void __launch_bounds__(512, 1) prep_gnn(
    const int* __restrict__ src, const int* __restrict__ dst,
    const float* __restrict__ W1, const float* __restrict__ b1,
    const float* __restrict__ W2, const float* __restrict__ b2,
    const float* __restrict__ Wa, const float* __restrict__ Wb,
    const float* __restrict__ Wc, const float* __restrict__ Wd,
    bf16* __restrict__ hgh, bf16* __restrict__ hgl)
{
    extern __shared__ unsigned char smraw[];
    const int bid = blockIdx.x;
    if (bid < 16) pwl_block(bid, smraw, W1, b1, W2);
    else          conv_block(bid - 16, 496, smraw, Wa, Wb, Wc, Wd);
    gnn_block(bid, smraw, src, dst, b2, hgh, hgl);
}

// ---------------------------------------------------------------------------
// bf16 hi/lo tensor-core GEMM, M-tile templated (32 or 64), N-tile 64.
// MMA rounds reordered across accumulators for ILP.
// ---------------------------------------------------------------------------
#define TSB 40

template <int MT>
__global__ void __launch_bounds__(256) gemm_bf16(
    const bf16* __restrict__ Ah, const bf16* __restrict__ Al,
    const bf16* __restrict__ Bh, const bf16* __restrict__ Bl,
    const float* __restrict__ bias,
    bf16* __restrict__ Oh, bf16* __restrict__ Ol,
    int K, int Nc)
{
    constexpr int MI = MT / 32;           // m16 tiles per warp
    __shared__ bf16 sAh[2][MT * TSB], sAl[2][MT * TSB];
    __shared__ bf16 sBh[2][64 * TSB], sBl[2][64 * TSB];

    const int tid  = threadIdx.x;
    const int lane = tid & 31;
    const int wid  = tid >> 5;
    const int wm   = wid & 1;
    const int wn   = wid >> 1;
    const int row0 = blockIdx.y * MT, col0 = blockIdx.x * 64;

    const int th  = tid & 127;
    const int lr  = th >> 2;
    const int lc  = (th & 3) * 8;
    const bool pl = (tid < 128);

    const bf16* gA = (pl ? Ah : Al) + (size_t)(row0 + lr) * K + lc;
    const bf16* gB = (pl ? Bh : Bl) + (size_t)(col0 + lr) * K + lc;
    bf16* dA0 = (pl ? sAh[0] : sAl[0]) + lr * TSB + lc;
    bf16* dB0 = (pl ? sBh[0] : sBl[0]) + lr * TSB + lc;
    bf16* dA1 = (pl ? sAh[1] : sAl[1]) + lr * TSB + lc;
    bf16* dB1 = (pl ? sBh[1] : sBl[1]) + lr * TSB + lc;

    float c[MI][2][4];
    #pragma unroll
    for (int mi = 0; mi < MI; mi++)
        #pragma unroll
        for (int ni = 0; ni < 2; ni++)
            #pragma unroll
            for (int q = 0; q < 4; q++) c[mi][ni][q] = 0.0f;

    cp16(dA0, gA);
    if (MT == 64) cp16(dA0 + 32 * TSB, gA + (size_t)32 * K);
    cp16(dB0, gB);  cp16(dB0 + 32 * TSB, gB + (size_t)32 * K);
    cp_commit();

    const int nkt = K >> 5;
    const int frow = lane & 15;
    const int fk   = (lane >> 4) * 8;
    int buf = 0;

    for (int kt = 0; kt < nkt; kt++) {
        if (kt + 1 < nkt) {
            const bf16* gA1 = gA + (size_t)(kt + 1) * 32;
            const bf16* gB1 = gB + (size_t)(kt + 1) * 32;
            bf16* dA = buf ? dA0 : dA1;
            bf16* dB = buf ? dB0 : dB1;
            cp16(dA, gA1);
            if (MT == 64) cp16(dA + 32 * TSB, gA1 + (size_t)32 * K);
            cp16(dB, gB1); cp16(dB + 32 * TSB, gB1 + (size_t)32 * K);
            cp_commit();
            cp_wait<1>();
        } else {
            cp_wait<0>();
        }
        __syncthreads();

        #pragma unroll
        for (int ks = 0; ks < 32; ks += 16) {
            unsigned ah[MI][4], al[MI][4], bh[4], bl[4];
            #pragma unroll
            for (int mi = 0; mi < MI; mi++) {
                int ro = (wm * (MT / 2) + mi * 16 + frow) * TSB + ks + fk;
                ldsm4(ah[mi], &sAh[buf][ro]);
                ldsm4(al[mi], &sAl[buf][ro]);
            }
            {
                int no = (wn * 16 + frow) * TSB + ks + fk;
                ldsm4(bh, &sBh[buf][no]);
                ldsm4(bl, &sBl[buf][no]);
            }
            // rounds across accumulators: hh, hl, lh
            #pragma unroll
            for (int mi = 0; mi < MI; mi++) {
                mma_bf16(c[mi][0], ah[mi], bh[0], bh[2]);
                mma_bf16(c[mi][1], ah[mi], bh[1], bh[3]);
            }
            #pragma unroll
            for (int mi = 0; mi < MI; mi++) {
                mma_bf16(c[mi][0], ah[mi], bl[0], bl[2]);
                mma_bf16(c[mi][1], ah[mi], bl[1], bl[3]);
            }
            #pragma unroll
            for (int mi = 0; mi < MI; mi++) {
                mma_bf16(c[mi][0], al[mi], bh[0], bh[2]);
                mma_bf16(c[mi][1], al[mi], bh[1], bh[3]);
            }
        }
        __syncthreads();
        buf ^= 1;
    }

    const int g  = lane >> 2;
    const int tg = lane & 3;
    #pragma unroll
    for (int mi = 0; mi < MI; mi++) {
        #pragma unroll
        for (int ni = 0; ni < 2; ni++) {
            int r  = row0 + wm * (MT / 2) + mi * 16 + g;
            int cc = col0 + wn * 16 + ni * 8 + tg * 2;
            float2 bv = *(const float2*)(bias + cc);
            #pragma unroll
            for (int half = 0; half < 2; half++) {
                int rr = r + half * 8;
                float vx = fmaxf(c[mi][ni][half * 2 + 0] + bv.x, 0.0f);
                float vy = fmaxf(c[mi][ni][half * 2 + 1] + bv.y, 0.0f);
                bf16 hx = __float2bfloat16(vx);
                bf16 hy = __float2bfloat16(vy);
                __nv_bfloat162 hp(hx, hy);
                __nv_bfloat162 lp(__float2bfloat16(vx - __bfloat162float(hx)),
                                  __float2bfloat16(vy - __bfloat162float(hy)));
                *(__nv_bfloat162*)(Oh + (size_t)rr * Nc + cc) = hp;
                *(__nv_bfloat162*)(Ol + (size_t)rr * Nc + cc) = lp;
            }
        }
    }
}

// ---------------------------------------------------------------------------
// Final layer + flag reset for the next replay.
// ---------------------------------------------------------------------------
__global__ void __launch_bounds__(256) head_softmax(
    const bf16* __restrict__ Ah, const bf16* __restrict__ Al,
    const float* __restrict__ We, const float* __restrict__ be,
    float* __restrict__ out)
{
    if (blockIdx.x == 0 && threadIdx.x == 0) g_pwl_flag = 0;

    __shared__ float Ws[512 * 10];
    const int tid = threadIdx.x;
    for (int i = tid; i < 512 * 10; i += 256) Ws[i] = We[i];
    __syncthreads();
    const int lane = tid & 31, w = tid >> 5;
    const int row = blockIdx.x * 8 + w;

    float acc[10];
    #pragma unroll
    for (int c = 0; c < 10; c++) acc[c] = 0.0f;
    for (int k = lane; k < 512; k += 32) {
        float a = __bfloat162float(Ah[row * 512 + k]) +
                  __bfloat162float(Al[row * 512 + k]);
        #pragma unroll
        for (int c = 0; c < 10; c++) acc[c] = fmaf(a, Ws[k * 10 + c], acc[c]);
    }
    #pragma unroll
    for (int c = 0; c < 10; c++) {
        #pragma unroll
        for (int o = 16; o > 0; o >>= 1)
            acc[c] += __shfl_xor_sync(0xffffffffu, acc[c], o);
    }
    if (lane == 0) {
        float v[10], mx = -1e30f;
        #pragma unroll
        for (int c = 0; c < 10; c++) { v[c] = acc[c] + be[c]; mx = fmaxf(mx, v[c]); }
        float s = 0.0f;
        #pragma unroll
        for (int c = 0; c < 10; c++) { v[c] = __expf(v[c] - mx); s += v[c]; }
        float inv = 1.0f / s;
        #pragma unroll
        for (int c = 0; c < 10; c++) out[row * 10 + c] = v[c] * inv;
    }
}

// ---------------------------------------------------------------------------
extern "C" void kernel_launch(void* const* d_in, const int* in_sizes, int n_in,
                              void* d_out, int out_size)
{
    const int*   src = (const int*)  d_in[0];
    const int*   dst = (const int*)  d_in[1];
    const float* W1  = (const float*)d_in[2];
    const float* b1  = (const float*)d_in[3];
    const float* W2  = (const float*)d_in[4];
    const float* b2  = (const float*)d_in[5];
    const float* Wa  = (const float*)d_in[6];
    const float* ba  = (const float*)d_in[7];
    const float* Wb  = (const float*)d_in[8];
    const float* bb  = (const float*)d_in[9];
    const float* Wc  = (const float*)d_in[10];
    const float* bc  = (const float*)d_in[11];
    const float* Wd  = (const float*)d_in[12];
    const float* bd  = (const float*)d_in[13];
    const float* We  = (const float*)d_in[14];
    const float* be  = (const float*)d_in[15];
    float* out = (float*)d_out;

    bf16 *hgh, *hgl, *x1h, *x1l, *x2h, *x2l, *x3h, *x3l, *x4h, *x4l;
    bf16 *wah, *wal, *wbh, *wbl, *wch, *wcl, *wdh, *wdl;
    cudaGetSymbolAddress((void**)&hgh, g_hgh); cudaGetSymbolAddress((void**)&hgl, g_hgl);
    cudaGetSymbolAddress((void**)&x1h, g_x1h); cudaGetSymbolAddress((void**)&x1l, g_x1l);
    cudaGetSymbolAddress((void**)&x2h, g_x2h); cudaGetSymbolAddress((void**)&x2l, g_x2l);
    cudaGetSymbolAddress((void**)&x3h, g_x3h); cudaGetSymbolAddress((void**)&x3l, g_x3l);
    cudaGetSymbolAddress((void**)&x4h, g_x4h); cudaGetSymbolAddress((void**)&x4l, g_x4l);
    cudaGetSymbolAddress((void**)&wah, g_wta_h); cudaGetSymbolAddress((void**)&wal, g_wta_l);
    cudaGetSymbolAddress((void**)&wbh, g_wtb_h); cudaGetSymbolAddress((void**)&wbl, g_wtb_l);
    cudaGetSymbolAddress((void**)&wch, g_wtc_h); cudaGetSymbolAddress((void**)&wcl, g_wtc_l);
    cudaGetSymbolAddress((void**)&wdh, g_wtd_h); cudaGetSymbolAddress((void**)&wdl, g_wtd_l);

    const int SMEM = 224 * CS * 2 + 2 * 208 * TSN * 2
                   + 4 * 224 * 4 + 256 * 4 + 448 * 4 + 224;
    cudaFuncSetAttribute(prep_gnn, cudaFuncAttributeMaxDynamicSharedMemorySize, SMEM);

    prep_gnn<<<512, 512, SMEM>>>(src, dst, W1, b1, W2, b2, Wa, Wb, Wc, Wd, hgh, hgl);

    gemm_bf16<32><<<dim3(512 / 64,  512 / 32), 256>>>(hgh, hgl, wah, wal, ba, x1h, x1l, 128,  512);
    gemm_bf16<64><<<dim3(1024 / 64, 512 / 64), 256>>>(x1h, x1l, wbh, wbl, bb, x2h, x2l, 512,  1024);
    gemm_bf16<64><<<dim3(1024 / 64, 512 / 64), 256>>>(x2h, x2l, wch, wcl, bc, x3h, x3l, 1024, 1024);
    gemm_bf16<32><<<dim3(512 / 64,  512 / 32), 256>>>(x3h, x3l, wdh, wdl, bd, x4h, x4l, 1024, 512);

    head_softmax<<<64, 256>>>(x4h, x4l, We, be, out);
}